// round 6
// baseline (speedup 1.0000x reference)
#include <cuda_runtime.h>
#include <cuda_bf16.h>
#include <cstdint>
#include <math.h>

// tcgen05 is only available in the arch-specific ("a") compilation pass.
#if defined(__CUDA_ARCH_FEAT_SM103_ALL) || defined(__CUDA_ARCH_FEAT_SM100_ALL) || \
    defined(__CUDA_ARCH_FEAT_SM110_ALL) || defined(__CUDA_ARCH_FEAT_SM101_ALL)
#define HAS_TCGEN05 1
#else
#define HAS_TCGEN05 0
#endif

// ---------------- scratch (allocation-free rule) ----------------
// fp32 buffers (scores both paths; rest fallback-only)
__device__ float g_S[32L * 512 * 1024];      // scores (both paths)
__device__ float g_Z[32L * 512 * 1024];      // fallback Z
__device__ float g_C[32L * 512 * 1024];      // fallback C
__device__ float g_encT[32L * 1024 * 1024];  // fallback encT

// bf16 split planes, SW128-swizzled 128x64 tile layout (a-path)
#define QP_N   (16384L * 1024)
#define WIP_N  (1024L * 1024)
#define EP_N   (32L * 1024 * 1024)
#define ZP_N   (16384L * 1024)
#define PP_N   (16384L * 1024)
#define ETP_N  (32L * 1024 * 1024)
#define CP_N   (16384L * 1024)
#define WOP_N  (1024L * 2048)
__device__ __nv_bfloat16 g_qP [3 * QP_N];
__device__ __nv_bfloat16 g_wiP[3 * WIP_N];
__device__ __nv_bfloat16 g_eP [3 * EP_N];
__device__ __nv_bfloat16 g_zP [3 * ZP_N];
__device__ __nv_bfloat16 g_pP [2 * PP_N];
__device__ __nv_bfloat16 g_etP[2 * ETP_N];
__device__ __nv_bfloat16 g_cP [2 * CP_N];
__device__ __nv_bfloat16 g_woP[2 * WOP_N];

// ---------------- common helpers ----------------
__device__ __forceinline__ uint32_t swz(uint32_t bo) { return bo ^ ((bo >> 3) & 0x70); }
__device__ __forceinline__ uint32_t pack2(float a, float b) {
    __nv_bfloat162 p = __halves2bfloat162(__float2bfloat16_rn(a), __float2bfloat16_rn(b));
    return *(uint32_t*)&p;
}

#if HAS_TCGEN05
// ---------------- PTX helpers ----------------
__device__ __forceinline__ uint32_t smem_u32(const void* p) {
    uint32_t a;
    asm("{ .reg .u64 t; cvta.to.shared.u64 t, %1; cvt.u32.u64 %0, t; }" : "=r"(a) : "l"(p));
    return a;
}
__device__ __forceinline__ uint32_t elect_one() {
    uint32_t pred;
    asm volatile("{\n\t.reg .pred p;\n\telect.sync _|p, 0xFFFFFFFF;\n\tselp.b32 %0, 1, 0, p;\n\t}"
                 : "=r"(pred));
    return pred;
}

#define MBARRIER_INIT(addr, cnt) \
    asm volatile("mbarrier.init.shared.b64 [%0], %1;" :: "r"(addr), "r"(cnt) : "memory")

#define MBARRIER_WAIT_PARITY(mbar_smem_addr, phase_parity) do { \
    uint32_t _mbar = (uint32_t)(mbar_smem_addr); \
    uint32_t _parity = (uint32_t)(phase_parity); \
    uint32_t _done; \
    asm volatile( \
        "{\n\t.reg .pred p;\n\t" \
        "mbarrier.try_wait.parity.acquire.cta.shared::cta.b64 p, [%1], %2;\n\t" \
        "selp.b32 %0, 1, 0, p;\n\t}" \
        : "=r"(_done) : "r"(_mbar), "r"(_parity) : "memory"); \
    if (!_done) { \
        asm volatile( \
            "{\n\t.reg .pred P1;\n\t" \
            "WAIT_LOOP_%=:\n\t" \
            "mbarrier.try_wait.parity.acquire.cta.shared::cta.b64 P1, [%0], %1, 0x989680;\n\t" \
            "@P1 bra.uni WAIT_DONE_%=;\n\t" \
            "bra.uni WAIT_LOOP_%=;\n\t" \
            "WAIT_DONE_%=:\n\t}" \
            :: "r"(_mbar), "r"(_parity) : "memory"); \
    } \
} while (0)

#define TCGEN05_ALLOC(smem_addr, n) \
    asm volatile("tcgen05.alloc.cta_group::1.sync.aligned.shared::cta.b32 [%0], %1;" \
                 :: "r"((uint32_t)(smem_addr)), "r"((uint32_t)(n)) : "memory")
#define TCGEN05_DEALLOC(tm, n) \
    asm volatile("tcgen05.dealloc.cta_group::1.sync.aligned.b32 %0, %1;" :: "r"(tm), "r"((uint32_t)(n)))
#define TCGEN05_RELINQ() \
    asm volatile("tcgen05.relinquish_alloc_permit.cta_group::1.sync.aligned;")
#define TCGEN05_COMMIT(mb) \
    asm volatile("tcgen05.commit.cta_group::1.mbarrier::arrive::one.shared::cluster.b64 [%0];" \
                 :: "r"((uint32_t)(mb)) : "memory")
#define TCGEN05_FENCE_AFTER() asm volatile("tcgen05.fence::after_thread_sync;" ::: "memory")
#define TCGEN05_WAIT_LD()     asm volatile("tcgen05.wait::ld.sync.aligned;" ::: "memory")
#define FENCE_PROXY_ASYNC()   asm volatile("fence.proxy.async.shared::cta;" ::: "memory")

#define TCGEN05_LD_X32(r, tm) \
    asm volatile( \
        "tcgen05.ld.sync.aligned.32x32b.x32.b32 " \
        "{%0, %1, %2, %3, %4, %5, %6, %7, %8, %9, %10, %11, %12, %13, %14, %15, " \
        " %16, %17, %18, %19, %20, %21, %22, %23, %24, %25, %26, %27, %28, %29, %30, %31}, [%32];" \
        : "=r"((r)[0]),  "=r"((r)[1]),  "=r"((r)[2]),  "=r"((r)[3]), \
          "=r"((r)[4]),  "=r"((r)[5]),  "=r"((r)[6]),  "=r"((r)[7]), \
          "=r"((r)[8]),  "=r"((r)[9]),  "=r"((r)[10]), "=r"((r)[11]), \
          "=r"((r)[12]), "=r"((r)[13]), "=r"((r)[14]), "=r"((r)[15]), \
          "=r"((r)[16]), "=r"((r)[17]), "=r"((r)[18]), "=r"((r)[19]), \
          "=r"((r)[20]), "=r"((r)[21]), "=r"((r)[22]), "=r"((r)[23]), \
          "=r"((r)[24]), "=r"((r)[25]), "=r"((r)[26]), "=r"((r)[27]), \
          "=r"((r)[28]), "=r"((r)[29]), "=r"((r)[30]), "=r"((r)[31]) \
        : "r"(tm))

// SW128 SMEM descriptor (Blackwell): layout=2, version=1, SBO=64, LBO=1
static constexpr uint64_t DESC_BASE =
    (uint64_t(2) << 61) | (uint64_t(1) << 46) | (uint64_t(64) << 32) | (uint64_t(1) << 16);
__device__ __forceinline__ uint64_t make_desc(uint32_t addr) {
    return DESC_BASE | ((uint64_t)(addr >> 4) & 0x3FFF);
}

// cg1 SS bf16 MMA (f32 accum)
__device__ __forceinline__ void mma_ss(uint32_t d, uint64_t ad, uint64_t bd,
                                       uint32_t idesc, bool acc) {
    uint32_t e = acc ? 1u : 0u;
    asm volatile(
        "{\n\t.reg .pred p;\n\tsetp.ne.u32 p, %4, 0;\n\t"
        "tcgen05.mma.cta_group::1.kind::f16 [%0], %1, %2, %3, {%5, %5, %5, %5}, p;\n\t}"
        :: "r"(d), "l"(ad), "l"(bd), "r"(idesc), "r"(e), "r"(0u) : "memory");
}

// idesc: dtype=F32, a=BF16, b=BF16, N=128, M=128 (K-major both)
static constexpr uint32_t IDESC = (1u << 4) | (1u << 7) | (1u << 10) | (16u << 17) | (8u << 24);

// 16KB tile copy gmem->smem (identical swizzled layouts; pure coalesced copy)
__device__ __forceinline__ void copy16k(char* dst, const char* __restrict__ src, int tid) {
    const uint4* s = (const uint4*)(src + tid * 64);
    uint4* d = (uint4*)(dst + tid * 64);
    uint4 v0 = s[0], v1 = s[1], v2 = s[2], v3 = s[3];
    d[0] = v0; d[1] = v1; d[2] = v2; d[3] = v3;
}
#endif  // HAS_TCGEN05

// ---------------- split kernels: fp32 -> bf16 planes in swizzled tile layout ----------------
// tile (128 rows x 64 cols); tileIdx = ((bz*gridDim.y)+by)*gridDim.x+bx; src row stride / batch offset.
template <int NSPLIT>
__global__ void split_planes(const float* __restrict__ src, long rowStride, long batchOff,
                             __nv_bfloat16* __restrict__ p0, __nv_bfloat16* __restrict__ p1,
                             __nv_bfloat16* __restrict__ p2)
{
    const int tid = threadIdx.x;
    const long tOff =
        (((long)blockIdx.z * gridDim.y + blockIdx.y) * gridDim.x + blockIdx.x) * 16384L;
    const float* s = src + (long)blockIdx.z * batchOff +
                     ((long)blockIdx.y * 128) * rowStride + blockIdx.x * 64;
    const int grp = tid >> 3, c8 = (tid & 7) << 3;
#pragma unroll
    for (int pr = 0; pr < 4; ++pr) {
        const int r = grp + (pr << 5);
        const float* rp = s + (long)r * rowStride + c8;
        const float4 v0 = *(const float4*)rp;
        const float4 v1 = *(const float4*)(rp + 4);
        const float x[8] = {v0.x, v0.y, v0.z, v0.w, v1.x, v1.y, v1.z, v1.w};
        unsigned w0[4], w1[4], w2[4];
#pragma unroll
        for (int j = 0; j < 4; ++j) {
            const float a = x[2 * j], b = x[2 * j + 1];
            const float a0 = __bfloat162float(__float2bfloat16_rn(a));
            const float b0 = __bfloat162float(__float2bfloat16_rn(b));
            const float ar = a - a0, br = b - b0;
            w0[j] = pack2(a, b);
            w1[j] = pack2(ar, br);
            if (NSPLIT == 3) {
                const float ar2 = ar - __bfloat162float(__float2bfloat16_rn(ar));
                const float br2 = br - __bfloat162float(__float2bfloat16_rn(br));
                w2[j] = pack2(ar2, br2);
            }
        }
        const uint32_t sw = swz((r << 7) + ((tid & 7) << 4));
        *(uint4*)((char*)p0 + tOff + sw) = make_uint4(w0[0], w0[1], w0[2], w0[3]);
        *(uint4*)((char*)p1 + tOff + sw) = make_uint4(w1[0], w1[1], w1[2], w1[3]);
        if (NSPLIT == 3)
            *(uint4*)((char*)p2 + tOff + sw) = make_uint4(w2[0], w2[1], w2[2], w2[3]);
    }
}

// ---------------- main GEMM ----------------
// C[m,n] (+= over NSEG segs) = sum_k A[m,k]*B[n,k], operands = pre-split swizzled bf16 tiles.
// EPI: 0 fp32 store, 1 tanh+bias fp32 store, 2 split-3 plane store, 3 split-2 plane store.
template <int NSPLIT, int NSEG, int EPI>
__global__ void __launch_bounds__(256, 1)
mma_gemm(const __nv_bfloat16* aP0, const __nv_bfloat16* aP1, const __nv_bfloat16* aP2,
         const __nv_bfloat16* a1P0, const __nv_bfloat16* a1P1,
         const __nv_bfloat16* bP0, const __nv_bfloat16* bP1, const __nv_bfloat16* bP2,
         int K64, int mBPB, int nBPB,
         __nv_bfloat16* oP0, __nv_bfloat16* oP1, __nv_bfloat16* oP2, int outCB,
         float* __restrict__ Cout, const float* __restrict__ bias, long sC, int ldc,
         const float* fA0, const float* fB0, const float* fA1, const float* fB1,
         long lda, long ldb, long sA, long sB)
{
    extern __shared__ char smem[];
    const int tid = threadIdx.x;
    const long bz = blockIdx.z;
    const int aBlk = (int)bz * mBPB + blockIdx.y;
    const int bBlk = (int)bz * nBPB + blockIdx.x;

#if HAS_TCGEN05
    constexpr int ARR = 16384;
    constexpr int STAGE = NSPLIT * 2 * ARR;
    const uint32_t sb = smem_u32(smem);
    const int wid = tid >> 5, lid = tid & 31;

    if (wid == 0) TCGEN05_ALLOC(sb, 128);
    __syncthreads();
    uint32_t tmem;
    asm volatile("ld.shared.b32 %0, [%1];" : "=r"(tmem) : "r"(sb));
    if (tid == 0) { MBARRIER_INIT(sb + 8, 1); MBARRIER_INIT(sb + 16, 1); }
    __syncthreads();

    const int total = NSEG * K64;
    int ph0 = 0, ph1 = 0;

    // chunk loader: pure tile copies from pre-split plane buffers
    auto load_chunk = [&](int c, char* st) {
        const char *ap0, *ap1, *ap2 = nullptr;
        long aOff;
        if (NSEG == 2 && c >= K64) {
            ap0 = (const char*)a1P0; ap1 = (const char*)a1P1;
            aOff = ((long)aBlk * K64 + (c - K64)) * 16384L;
        } else {
            ap0 = (const char*)aP0; ap1 = (const char*)aP1; ap2 = (const char*)aP2;
            aOff = ((long)aBlk * K64 + c) * 16384L;
        }
        const long bOff = ((long)bBlk * (NSEG * K64) + c) * 16384L;
        copy16k(st, ap0 + aOff, tid);
        copy16k(st + ARR, ap1 + aOff, tid);
        if (NSPLIT == 3) copy16k(st + 2 * ARR, ap2 + aOff, tid);
        copy16k(st + NSPLIT * ARR, (const char*)bP0 + bOff, tid);
        copy16k(st + (NSPLIT + 1) * ARR, (const char*)bP1 + bOff, tid);
        if (NSPLIT == 3) copy16k(st + 5 * ARR, (const char*)bP2 + bOff, tid);
    };

    load_chunk(0, smem + 1024);
    FENCE_PROXY_ASYNC();
    __syncthreads();

#pragma unroll 1
    for (int c = 0; c < total; ++c) {
        const int s = c & 1;
        if (wid == 0) {
            if (elect_one()) {
                const uint32_t stb = sb + 1024 + s * STAGE;
                uint64_t dA[3], dB[3];
#pragma unroll
                for (int i = 0; i < NSPLIT; ++i) {
                    dA[i] = make_desc(stb + i * ARR);
                    dB[i] = make_desc(stb + (NSPLIT + i) * ARR);
                }
#pragma unroll
                for (int k = 0; k < 4; ++k) {
                    const uint64_t off = (uint64_t)(k * 2);
                    const bool first = (c == 0) && (k == 0);
                    if (NSPLIT == 3) {
                        mma_ss(tmem, dA[2] + off, dB[0] + off, IDESC, !first);
                        mma_ss(tmem, dA[0] + off, dB[2] + off, IDESC, true);
                        mma_ss(tmem, dA[1] + off, dB[1] + off, IDESC, true);
                        mma_ss(tmem, dA[1] + off, dB[0] + off, IDESC, true);
                        mma_ss(tmem, dA[0] + off, dB[1] + off, IDESC, true);
                        mma_ss(tmem, dA[0] + off, dB[0] + off, IDESC, true);
                    } else {
                        mma_ss(tmem, dA[1] + off, dB[0] + off, IDESC, !first);
                        mma_ss(tmem, dA[0] + off, dB[1] + off, IDESC, true);
                        mma_ss(tmem, dA[0] + off, dB[0] + off, IDESC, true);
                    }
                }
                TCGEN05_COMMIT(sb + 8 + s * 8);
            }
        }
        if (c + 1 < total) {
            const int s2 = (c + 1) & 1;
            if (c + 1 >= 2) {
                if (s2 == 0) { MBARRIER_WAIT_PARITY(sb + 8, ph0); ph0 ^= 1; }
                else         { MBARRIER_WAIT_PARITY(sb + 16, ph1); ph1 ^= 1; }
            }
            load_chunk(c + 1, smem + 1024 + s2 * STAGE);
            FENCE_PROXY_ASYNC();
            __syncthreads();
        }
    }

    {
        const int sl = (total - 1) & 1;
        if (sl == 0) { MBARRIER_WAIT_PARITY(sb + 8, ph0); }
        else         { MBARRIER_WAIT_PARITY(sb + 16, ph1); }
    }
    TCGEN05_FENCE_AFTER();

    if (wid < 4) {
        const int r = wid * 32 + lid;  // row within 128-row tile
#pragma unroll 1
        for (int b4 = 0; b4 < 4; ++b4) {
            uint32_t rg[32];
            TCGEN05_LD_X32(rg, tmem + b4 * 32);
            TCGEN05_WAIT_LD();
            if (EPI <= 1) {
                const long m = (long)blockIdx.y * 128 + r;
                float* Crow = Cout + bz * sC + m * ldc + (long)blockIdx.x * 128;
#pragma unroll
                for (int j = 0; j < 32; j += 4) {
                    float4 v;
                    v.x = __uint_as_float(rg[j + 0]);
                    v.y = __uint_as_float(rg[j + 1]);
                    v.z = __uint_as_float(rg[j + 2]);
                    v.w = __uint_as_float(rg[j + 3]);
                    if (EPI == 1) {
                        const float* bb = bias + blockIdx.x * 128 + b4 * 32 + j;
                        v.x = tanhf(v.x + bb[0]);
                        v.y = tanhf(v.y + bb[1]);
                        v.z = tanhf(v.z + bb[2]);
                        v.w = tanhf(v.w + bb[3]);
                    }
                    *(float4*)(Crow + b4 * 32 + j) = v;
                }
            } else {
                // split-plane store
                const int chunk = ((blockIdx.x << 7) + (b4 << 5)) >> 6;
                const int cbase = (b4 & 1) << 5;
                const long tOff = ((long)aBlk * outCB + chunk) * 16384L;
#pragma unroll
                for (int j = 0; j < 32; j += 4) {
                    float v[4];
                    v[0] = __uint_as_float(rg[j + 0]);
                    v[1] = __uint_as_float(rg[j + 1]);
                    v[2] = __uint_as_float(rg[j + 2]);
                    v[3] = __uint_as_float(rg[j + 3]);
                    float hi[4], mid[4];
#pragma unroll
                    for (int q = 0; q < 4; ++q) {
                        hi[q] = __bfloat162float(__float2bfloat16_rn(v[q]));
                        mid[q] = v[q] - hi[q];
                    }
                    const uint32_t sw = swz((r << 7) + ((cbase + j) << 1));
                    *(uint2*)((char*)oP0 + tOff + sw) =
                        make_uint2(pack2(v[0], v[1]), pack2(v[2], v[3]));
                    *(uint2*)((char*)oP1 + tOff + sw) =
                        make_uint2(pack2(mid[0], mid[1]), pack2(mid[2], mid[3]));
                    if (EPI == 2) {
                        float lo[4];
#pragma unroll
                        for (int q = 0; q < 4; ++q)
                            lo[q] = mid[q] - __bfloat162float(__float2bfloat16_rn(mid[q]));
                        *(uint2*)((char*)oP2 + tOff + sw) =
                            make_uint2(pack2(lo[0], lo[1]), pack2(lo[2], lo[3]));
                    }
                }
            }
        }
    }
    __syncthreads();
    if (wid == 0) {
        TCGEN05_RELINQ();
        TCGEN05_DEALLOC(tmem, 128);
    }

#else  // ---------------- fp32 FFMA fallback (non-"a" pass) ----------------
    float (*As)[132] = (float(*)[132])smem;
    float (*Bs)[132] = (float(*)[132])(smem + 16 * 132 * 4);
    const int tx = tid & 15, ty = tid >> 4;
    const long m0 = (long)blockIdx.y * 128, n0 = (long)blockIdx.x * 128;
    const int K = K64 << 6;

    float acc[8][8];
#pragma unroll
    for (int i = 0; i < 8; i++)
#pragma unroll
        for (int j = 0; j < 8; j++) acc[i][j] = 0.0f;

    const int arow = tid >> 2, ac4 = (tid & 3) * 4;
#pragma unroll
    for (int seg = 0; seg < NSEG; ++seg) {
        const float* A = (seg == 0 ? fA0 : fA1) + bz * sA + m0 * lda;
        const float* B = (seg == 0 ? fB0 : fB1) + bz * sB + n0 * ldb;
        for (int kt = 0; kt < K; kt += 16) {
#pragma unroll
            for (int rr = 0; rr < 2; ++rr) {
                const int row = arow + rr * 64;
                float4 va = *(const float4*)(A + (long)row * lda + kt + ac4);
                As[ac4 + 0][row] = va.x; As[ac4 + 1][row] = va.y;
                As[ac4 + 2][row] = va.z; As[ac4 + 3][row] = va.w;
                float4 vb = *(const float4*)(B + (long)row * ldb + kt + ac4);
                Bs[ac4 + 0][row] = vb.x; Bs[ac4 + 1][row] = vb.y;
                Bs[ac4 + 2][row] = vb.z; Bs[ac4 + 3][row] = vb.w;
            }
            __syncthreads();
#pragma unroll
            for (int kk = 0; kk < 16; ++kk) {
                float a[8], b[8];
                *(float4*)&a[0] = *(const float4*)&As[kk][ty * 8];
                *(float4*)&a[4] = *(const float4*)&As[kk][ty * 8 + 4];
                *(float4*)&b[0] = *(const float4*)&Bs[kk][tx * 8];
                *(float4*)&b[4] = *(const float4*)&Bs[kk][tx * 8 + 4];
#pragma unroll
                for (int i = 0; i < 8; i++)
#pragma unroll
                    for (int j = 0; j < 8; j++)
                        acc[i][j] = fmaf(a[i], b[j], acc[i][j]);
            }
            __syncthreads();
        }
    }
    float* Cp = Cout + bz * sC + (m0 + ty * 8) * ldc + n0 + tx * 8;
#pragma unroll
    for (int i = 0; i < 8; i++) {
#pragma unroll
        for (int j = 0; j < 8; j += 4) {
            float4 v;
            v.x = acc[i][j + 0]; v.y = acc[i][j + 1];
            v.z = acc[i][j + 2]; v.w = acc[i][j + 3];
            if (EPI == 1) {
                const long nb = n0 + tx * 8 + j;
                v.x = tanhf(v.x + bias[nb + 0]);
                v.y = tanhf(v.y + bias[nb + 1]);
                v.z = tanhf(v.z + bias[nb + 2]);
                v.w = tanhf(v.w + bias[nb + 3]);
            }
            *(float4*)(Cp + (long)i * ldc + j) = v;
        }
    }
#endif
}

// ---------------- softmax over S=1024 (==0 -> -inf fill); a-path emits split-2 planes ----------------
__global__ void softmax_kernel(float* __restrict__ S,
                               __nv_bfloat16* __restrict__ p0, __nv_bfloat16* __restrict__ p1)
{
    const long row = blockIdx.x;
    float* p = S + (row << 10);
    const int tid = threadIdx.x;

    float4 xv = *(const float4*)(p + tid * 4);
    float v[4] = {xv.x, xv.y, xv.z, xv.w};
    float mx = -INFINITY;
#pragma unroll
    for (int i = 0; i < 4; i++) {
        if (v[i] == 0.0f) v[i] = -INFINITY;
        mx = fmaxf(mx, v[i]);
    }
    __shared__ float red[8];
#pragma unroll
    for (int o = 16; o; o >>= 1) mx = fmaxf(mx, __shfl_xor_sync(0xffffffffu, mx, o));
    if ((tid & 31) == 0) red[tid >> 5] = mx;
    __syncthreads();
    const float m = fmaxf(fmaxf(fmaxf(red[0], red[1]), fmaxf(red[2], red[3])),
                          fmaxf(fmaxf(red[4], red[5]), fmaxf(red[6], red[7])));
    __syncthreads();
    float s = 0.0f;
#pragma unroll
    for (int i = 0; i < 4; i++) { v[i] = expf(v[i] - m); s += v[i]; }
#pragma unroll
    for (int o = 16; o; o >>= 1) s += __shfl_xor_sync(0xffffffffu, s, o);
    if ((tid & 31) == 0) red[tid >> 5] = s;
    __syncthreads();
    const float inv = 1.0f / (red[0] + red[1] + red[2] + red[3] +
                              red[4] + red[5] + red[6] + red[7]);
#pragma unroll
    for (int i = 0; i < 4; i++) v[i] *= inv;

#if HAS_TCGEN05
    // write split-2 planes in swizzled tile layout: tile (row/128, (tid*4)/64)
    const int mBlk = (int)(row >> 7);
    const int r = (int)(row & 127);
    const int chunk = tid >> 4;
    const int cIn = (tid << 2) & 63;
    const long tOff = ((long)mBlk * 16 + chunk) * 16384L;
    float hi[4], lo[4];
#pragma unroll
    for (int q = 0; q < 4; ++q) {
        hi[q] = __bfloat162float(__float2bfloat16_rn(v[q]));
        lo[q] = v[q] - hi[q];
    }
    const uint32_t sw = swz((r << 7) + (cIn << 1));
    *(uint2*)((char*)p0 + tOff + sw) = make_uint2(pack2(v[0], v[1]), pack2(v[2], v[3]));
    *(uint2*)((char*)p1 + tOff + sw) = make_uint2(pack2(lo[0], lo[1]), pack2(lo[2], lo[3]));
#else
    *(float4*)(p + tid * 4) = make_float4(v[0], v[1], v[2], v[3]);
#endif
}

// ---------------- enc [S,B,H] -> encT; a-path emits split-2 swizzled planes ----------------
__global__ void transpose_enc(const float* __restrict__ enc, float* __restrict__ encT,
                              __nv_bfloat16* __restrict__ tp0, __nv_bfloat16* __restrict__ tp1)
{
    __shared__ float t[32][33];
    const int b  = blockIdx.z;
    const int s0 = blockIdx.x << 5;
    const int h0 = blockIdx.y << 5;
    const int tx = threadIdx.x, ty = threadIdx.y;  // 32x8
    const int tid = ty * 32 + tx;
#pragma unroll
    for (int j = 0; j < 4; ++j) {
        const int s = s0 + ty + j * 8;
        t[ty + j * 8][tx] = enc[(long)s * 32768 + b * 1024 + h0 + tx];
    }
    __syncthreads();
#if HAS_TCGEN05
    const int hIdx = tid >> 4;          // 0..15
    const int sp   = (tid & 15) << 1;   // 0,2,..,30
#pragma unroll
    for (int q = 0; q < 2; ++q) {
        const int hl = hIdx + (q << 4);
        const float v0 = t[sp][hl], v1 = t[sp + 1][hl];
        const int h = h0 + hl, s = s0 + sp;
        const int r = h & 127, hBlk = h >> 7;
        const int c = s & 63, sChunk = s >> 6;
        const long tOff = (((long)b * 8 + hBlk) * 16 + sChunk) * 16384L;
        const float h0f = __bfloat162float(__float2bfloat16_rn(v0));
        const float h1f = __bfloat162float(__float2bfloat16_rn(v1));
        const uint32_t sw = swz((r << 7) + (c << 1));
        *(uint32_t*)((char*)tp0 + tOff + sw) = pack2(v0, v1);
        *(uint32_t*)((char*)tp1 + tOff + sw) = pack2(v0 - h0f, v1 - h1f);
    }
#else
#pragma unroll
    for (int j = 0; j < 4; ++j) {
        const int h = h0 + ty + j * 8;
        encT[((long)b << 20) + ((long)h << 10) + s0 + tx] = t[tx][ty + j * 8];
    }
#endif
}

// ---------------- launch ----------------
extern "C" void kernel_launch(void* const* d_in, const int* in_sizes, int n_in,
                              void* d_out, int out_size)
{
    const float* query = (const float*)d_in[0];  // [B,T,H]
    const float* enc   = (const float*)d_in[1];  // [S,B,H]
    const float* W_in  = (const float*)d_in[3];  // [H,H]
    const float* W_out = (const float*)d_in[4];  // [H,2H]
    const float* b_out = (const float*)d_in[5];  // [H]
    float* out = (float*)d_out;                  // [B,T,H]

    float *S, *Zf, *Cf, *encTf;
    cudaGetSymbolAddress((void**)&S, g_S);
    cudaGetSymbolAddress((void**)&Zf, g_Z);
    cudaGetSymbolAddress((void**)&Cf, g_C);
    cudaGetSymbolAddress((void**)&encTf, g_encT);
    __nv_bfloat16 *qP, *wiP, *eP, *zP, *pP, *etP, *cP, *woP;
    cudaGetSymbolAddress((void**)&qP, g_qP);
    cudaGetSymbolAddress((void**)&wiP, g_wiP);
    cudaGetSymbolAddress((void**)&eP, g_eP);
    cudaGetSymbolAddress((void**)&zP, g_zP);
    cudaGetSymbolAddress((void**)&pP, g_pP);
    cudaGetSymbolAddress((void**)&etP, g_etP);
    cudaGetSymbolAddress((void**)&cP, g_cP);
    cudaGetSymbolAddress((void**)&woP, g_woP);

    const int SM3 = 1024 + 2 * 6 * 16384;  // 197,632 B
    const int SM2 = 1024 + 2 * 4 * 16384;  // 132,096 B
    cudaFuncSetAttribute(mma_gemm<3, 1, 2>, cudaFuncAttributeMaxDynamicSharedMemorySize, SM3);
    cudaFuncSetAttribute(mma_gemm<3, 1, 0>, cudaFuncAttributeMaxDynamicSharedMemorySize, SM3);
    cudaFuncSetAttribute(mma_gemm<2, 1, 3>, cudaFuncAttributeMaxDynamicSharedMemorySize, SM2);
    cudaFuncSetAttribute(mma_gemm<2, 2, 1>, cudaFuncAttributeMaxDynamicSharedMemorySize, SM2);

    // -------- precompute split planes (a-path inputs) --------
    split_planes<3><<<dim3(16, 128, 1), 256>>>(query, 1024, 0,
        qP, qP + QP_N, qP + 2 * QP_N);
    split_planes<3><<<dim3(16, 8, 1), 256>>>(W_in, 1024, 0,
        wiP, wiP + WIP_N, wiP + 2 * WIP_N);
    split_planes<3><<<dim3(16, 8, 32), 256>>>(enc, 32768, 1024,
        eP, eP + EP_N, eP + 2 * EP_N);
    split_planes<2><<<dim3(32, 8, 1), 256>>>(W_out, 2048, 0,
        woP, woP + WOP_N, nullptr);
    transpose_enc<<<dim3(32, 32, 32), dim3(32, 8)>>>(enc, encTf, etP, etP + ETP_N);

    // 1) Z = Q @ W_in^T -> split-3 planes (EPI=2)
    mma_gemm<3, 1, 2><<<dim3(8, 128, 1), 256, SM3>>>(
        qP, qP + QP_N, qP + 2 * QP_N, nullptr, nullptr,
        wiP, wiP + WIP_N, wiP + 2 * WIP_N,
        16, 128, 8,
        zP, zP + ZP_N, zP + 2 * ZP_N, 16,
        Zf, nullptr, 0, 1024,
        query, W_in, nullptr, nullptr, 1024, 1024, 0, 0);

    // 2) scores[b] = Z[b] @ enc[:,b,:]^T -> fp32 (EPI=0)
    mma_gemm<3, 1, 0><<<dim3(8, 4, 32), 256, SM3>>>(
        zP, zP + ZP_N, zP + 2 * ZP_N, nullptr, nullptr,
        eP, eP + EP_N, eP + 2 * EP_N,
        16, 4, 8,
        nullptr, nullptr, nullptr, 0,
        S, nullptr, 512L * 1024, 1024,
        Zf, enc, nullptr, nullptr, 1024, 32768, 512L * 1024, 1024);

    // 3) softmax (with ==0 -> -inf quirk) -> split-2 planes
    softmax_kernel<<<16384, 256>>>(S, pP, pP + PP_N);

    // 4) c[b] = P[b] @ encT[b]^T -> split-2 planes (EPI=3)
    mma_gemm<2, 1, 3><<<dim3(8, 4, 32), 256, SM2>>>(
        pP, pP + PP_N, nullptr, nullptr, nullptr,
        etP, etP + ETP_N, nullptr,
        16, 4, 8,
        cP, cP + CP_N, nullptr, 16,
        Cf, nullptr, 512L * 1024, 1024,
        S, encTf, nullptr, nullptr, 1024, 1024, 512L * 1024, 1024L * 1024);

    // 5) out = tanh(C @ Wout1^T + Q @ Wout2^T + b)   (EPI=1, NSEG=2)
    mma_gemm<2, 2, 1><<<dim3(8, 128, 1), 256, SM2>>>(
        cP, cP + CP_N, nullptr, qP, qP + QP_N,
        woP, woP + WOP_N, nullptr,
        16, 128, 8,
        nullptr, nullptr, nullptr, 0,
        out, b_out, 0, 1024,
        Cf, W_out, query, W_out + 1024, 1024, 2048, 0, 0);
}

// round 10
// speedup vs baseline: 1.3650x; 1.3650x over previous
#include <cuda_runtime.h>
#include <cuda_bf16.h>
#include <cstdint>
#include <math.h>

// tcgen05 is only available in the arch-specific ("a") compilation pass.
#if defined(__CUDA_ARCH_FEAT_SM103_ALL) || defined(__CUDA_ARCH_FEAT_SM100_ALL) || \
    defined(__CUDA_ARCH_FEAT_SM110_ALL) || defined(__CUDA_ARCH_FEAT_SM101_ALL)
#define HAS_TCGEN05 1
#else
#define HAS_TCGEN05 0
#endif

// ---------------- scratch (allocation-free rule) ----------------
__device__ float g_Z[32L * 512 * 1024];      // 64MB
__device__ float g_S[32L * 512 * 1024];      // 64MB
__device__ float g_C[32L * 512 * 1024];      // 64MB
__device__ float g_encT[32L * 1024 * 1024];  // 128MB  [b][h][s]

#if HAS_TCGEN05
// ---------------- PTX helpers ----------------
__device__ __forceinline__ uint32_t smem_u32(const void* p) {
    uint32_t a;
    asm("{ .reg .u64 t; cvta.to.shared.u64 t, %1; cvt.u32.u64 %0, t; }" : "=r"(a) : "l"(p));
    return a;
}
__device__ __forceinline__ uint32_t elect_one() {
    uint32_t pred;
    asm volatile("{\n\t.reg .pred p;\n\telect.sync _|p, 0xFFFFFFFF;\n\tselp.b32 %0, 1, 0, p;\n\t}"
                 : "=r"(pred));
    return pred;
}

#define MBARRIER_INIT(addr, cnt) \
    asm volatile("mbarrier.init.shared.b64 [%0], %1;" :: "r"(addr), "r"(cnt) : "memory")

#define MBARRIER_WAIT_PARITY(mbar_smem_addr, phase_parity) do { \
    uint32_t _mbar = (uint32_t)(mbar_smem_addr); \
    uint32_t _parity = (uint32_t)(phase_parity); \
    uint32_t _done; \
    asm volatile( \
        "{\n\t.reg .pred p;\n\t" \
        "mbarrier.try_wait.parity.acquire.cta.shared::cta.b64 p, [%1], %2;\n\t" \
        "selp.b32 %0, 1, 0, p;\n\t}" \
        : "=r"(_done) : "r"(_mbar), "r"(_parity) : "memory"); \
    if (!_done) { \
        asm volatile( \
            "{\n\t.reg .pred P1;\n\t" \
            "WAIT_LOOP_%=:\n\t" \
            "mbarrier.try_wait.parity.acquire.cta.shared::cta.b64 P1, [%0], %1, 0x989680;\n\t" \
            "@P1 bra.uni WAIT_DONE_%=;\n\t" \
            "bra.uni WAIT_LOOP_%=;\n\t" \
            "WAIT_DONE_%=:\n\t}" \
            :: "r"(_mbar), "r"(_parity) : "memory"); \
    } \
} while (0)

#define TCGEN05_ALLOC(smem_addr, n) \
    asm volatile("tcgen05.alloc.cta_group::1.sync.aligned.shared::cta.b32 [%0], %1;" \
                 :: "r"((uint32_t)(smem_addr)), "r"((uint32_t)(n)) : "memory")
#define TCGEN05_DEALLOC(tm, n) \
    asm volatile("tcgen05.dealloc.cta_group::1.sync.aligned.b32 %0, %1;" :: "r"(tm), "r"((uint32_t)(n)))
#define TCGEN05_RELINQ() \
    asm volatile("tcgen05.relinquish_alloc_permit.cta_group::1.sync.aligned;")
#define TCGEN05_COMMIT(mb) \
    asm volatile("tcgen05.commit.cta_group::1.mbarrier::arrive::one.shared::cluster.b64 [%0];" \
                 :: "r"((uint32_t)(mb)) : "memory")
#define TCGEN05_FENCE_AFTER() asm volatile("tcgen05.fence::after_thread_sync;" ::: "memory")
#define TCGEN05_WAIT_LD()     asm volatile("tcgen05.wait::ld.sync.aligned;" ::: "memory")
#define FENCE_PROXY_ASYNC()   asm volatile("fence.proxy.async.shared::cta;" ::: "memory")

#define TCGEN05_LD_X32(r, tm) \
    asm volatile( \
        "tcgen05.ld.sync.aligned.32x32b.x32.b32 " \
        "{%0, %1, %2, %3, %4, %5, %6, %7, %8, %9, %10, %11, %12, %13, %14, %15, " \
        " %16, %17, %18, %19, %20, %21, %22, %23, %24, %25, %26, %27, %28, %29, %30, %31}, [%32];" \
        : "=r"((r)[0]),  "=r"((r)[1]),  "=r"((r)[2]),  "=r"((r)[3]), \
          "=r"((r)[4]),  "=r"((r)[5]),  "=r"((r)[6]),  "=r"((r)[7]), \
          "=r"((r)[8]),  "=r"((r)[9]),  "=r"((r)[10]), "=r"((r)[11]), \
          "=r"((r)[12]), "=r"((r)[13]), "=r"((r)[14]), "=r"((r)[15]), \
          "=r"((r)[16]), "=r"((r)[17]), "=r"((r)[18]), "=r"((r)[19]), \
          "=r"((r)[20]), "=r"((r)[21]), "=r"((r)[22]), "=r"((r)[23]), \
          "=r"((r)[24]), "=r"((r)[25]), "=r"((r)[26]), "=r"((r)[27]), \
          "=r"((r)[28]), "=r"((r)[29]), "=r"((r)[30]), "=r"((r)[31]) \
        : "r"(tm))

// SW128 SMEM descriptor (Blackwell): layout=2, version=1, SBO=64, LBO=1
static constexpr uint64_t DESC_BASE =
    (uint64_t(2) << 61) | (uint64_t(1) << 46) | (uint64_t(64) << 32) | (uint64_t(1) << 16);
__device__ __forceinline__ uint64_t make_desc(uint32_t addr) {
    return DESC_BASE | ((uint64_t)(addr >> 4) & 0x3FFF);
}

// cg1 SS bf16 MMA (f32 accum)
__device__ __forceinline__ void mma_ss(uint32_t d, uint64_t ad, uint64_t bd,
                                       uint32_t idesc, bool acc) {
    uint32_t e = acc ? 1u : 0u;
    asm volatile(
        "{\n\t.reg .pred p;\n\tsetp.ne.u32 p, %4, 0;\n\t"
        "tcgen05.mma.cta_group::1.kind::f16 [%0], %1, %2, %3, {%5, %5, %5, %5}, p;\n\t}"
        :: "r"(d), "l"(ad), "l"(bd), "r"(idesc), "r"(e), "r"(0u) : "memory");
}

// idesc: dtype=F32, a=BF16, b=BF16, N=128, M=128 (K-major both)
static constexpr uint32_t IDESC = (1u << 4) | (1u << 7) | (1u << 10) | (16u << 17) | (8u << 24);

// ---------------- tile loader: fp32 -> NSPLIT bf16 planes, SW128 swizzled ----------------
// tile = 128 rows x 64 cols; planes spaced 16KB apart starting at s0.
template <int NSPLIT>
__device__ __forceinline__ void load_tile(char* s0, const float* __restrict__ g,
                                          long ld, int tid) {
    const int grp = tid >> 3;     // 0..31 (row group)
    const int c8  = tid & 7;      // 8 fp32 elements each
#pragma unroll
    for (int p = 0; p < 4; ++p) {
        const int r = grp + (p << 5);
        const float* src = g + (long)r * ld + (c8 << 3);
        const float4 v0 = *(const float4*)(src);
        const float4 v1 = *(const float4*)(src + 4);
        const float x[8] = {v0.x, v0.y, v0.z, v0.w, v1.x, v1.y, v1.z, v1.w};
        unsigned w0[4], w1[4], w2[4];
#pragma unroll
        for (int j = 0; j < 4; ++j) {
            const float a = x[2 * j], b = x[2 * j + 1];
            const __nv_bfloat16 a0 = __float2bfloat16_rn(a);
            const __nv_bfloat16 b0 = __float2bfloat16_rn(b);
            const float ar = a - __bfloat162float(a0);
            const float br = b - __bfloat162float(b0);
            const __nv_bfloat16 a1 = __float2bfloat16_rn(ar);
            const __nv_bfloat16 b1 = __float2bfloat16_rn(br);
            __nv_bfloat162 p0 = __halves2bfloat162(a0, b0);
            __nv_bfloat162 p1 = __halves2bfloat162(a1, b1);
            w0[j] = *(unsigned*)&p0;
            w1[j] = *(unsigned*)&p1;
            if (NSPLIT == 3) {
                const float ar2 = ar - __bfloat162float(a1);
                const float br2 = br - __bfloat162float(b1);
                __nv_bfloat162 p2 =
                    __halves2bfloat162(__float2bfloat16_rn(ar2), __float2bfloat16_rn(br2));
                w2[j] = *(unsigned*)&p2;
            }
        }
        const uint32_t bo = (r << 7) + (c8 << 4);
        const uint32_t sw = bo ^ ((bo >> 3) & 0x70);
        *(uint4*)(s0 + sw)         = make_uint4(w0[0], w0[1], w0[2], w0[3]);
        *(uint4*)(s0 + 16384 + sw) = make_uint4(w1[0], w1[1], w1[2], w1[3]);
        if (NSPLIT == 3)
            *(uint4*)(s0 + 32768 + sw) = make_uint4(w2[0], w2[1], w2[2], w2[3]);
    }
}
#endif  // HAS_TCGEN05

// ---------------- main GEMM ----------------
// C[bz][m,n] (+= over NSEG segs) = sum_k A[m,k] * B[n,k]  (both operands K-contiguous)
// EPI: 0 = fp32 store, 1 = tanh(x + bias[n]) store.
// Single-stage SMEM buffer; 2 CTAs/SM provide the load/MMA overlap.
template <int NSPLIT, int NSEG, int EPI>
__global__ void __launch_bounds__(256, 2)
mma_gemm(const float* A0, const float* B0, const float* A1, const float* B1,
         int K64, long lda, long ldb, long sA, long sB, long sC,
         float* __restrict__ C, int ldc, const float* __restrict__ bias)
{
    extern __shared__ char smem[];
    const int tid = threadIdx.x;
    const long m0 = (long)blockIdx.y * 128;
    const long n0 = (long)blockIdx.x * 128;
    const long bz = blockIdx.z;

#if HAS_TCGEN05
    constexpr int ARR = 16384;
    const uint32_t sb = smem_u32(smem);
    const int wid = tid >> 5, lid = tid & 31;

    if (wid == 0) TCGEN05_ALLOC(sb, 128);
    __syncthreads();
    uint32_t tmem;
    asm volatile("ld.shared.b32 %0, [%1];" : "=r"(tmem) : "r"(sb));
    if (tid == 0) MBARRIER_INIT(sb + 8, 1);
    __syncthreads();

    const int total = NSEG * K64;
    int ph = 0;
    char* st = smem + 1024;

#pragma unroll 1
    for (int c = 0; c < total; ++c) {
        // load chunk c into the single stage (previous MMA already drained)
        const int seg = (NSEG == 2) ? (int)(c >= K64) : 0;
        const long kt = (long)(c - seg * K64) << 6;
        const float* Ag = (seg ? A1 : A0) + bz * sA + m0 * lda + kt;
        const float* Bg = (seg ? B1 : B0) + bz * sB + n0 * ldb + kt;
        load_tile<NSPLIT>(st, Ag, lda, tid);
        load_tile<NSPLIT>(st + NSPLIT * ARR, Bg, ldb, tid);
        FENCE_PROXY_ASYNC();
        __syncthreads();

        if (wid == 0) {
            if (elect_one()) {
                const uint32_t stb = sb + 1024;
                uint64_t dA[3], dB[3];
#pragma unroll
                for (int i = 0; i < NSPLIT; ++i) {
                    dA[i] = make_desc(stb + i * ARR);
                    dB[i] = make_desc(stb + (NSPLIT + i) * ARR);
                }
#pragma unroll
                for (int k = 0; k < 4; ++k) {
                    const uint64_t off = (uint64_t)(k * 2);
                    const bool first = (c == 0) && (k == 0);
                    if (NSPLIT == 3) {
                        mma_ss(tmem, dA[2] + off, dB[0] + off, IDESC, !first);
                        mma_ss(tmem, dA[0] + off, dB[2] + off, IDESC, true);
                        mma_ss(tmem, dA[1] + off, dB[1] + off, IDESC, true);
                        mma_ss(tmem, dA[1] + off, dB[0] + off, IDESC, true);
                        mma_ss(tmem, dA[0] + off, dB[1] + off, IDESC, true);
                        mma_ss(tmem, dA[0] + off, dB[0] + off, IDESC, true);
                    } else {
                        mma_ss(tmem, dA[1] + off, dB[0] + off, IDESC, !first);
                        mma_ss(tmem, dA[0] + off, dB[1] + off, IDESC, true);
                        mma_ss(tmem, dA[0] + off, dB[0] + off, IDESC, true);
                    }
                }
                TCGEN05_COMMIT(sb + 8);
            }
        }
        // all threads wait for this chunk's MMAs before overwriting the stage
        MBARRIER_WAIT_PARITY(sb + 8, ph);
        ph ^= 1;
    }
    TCGEN05_FENCE_AFTER();

    if (wid < 4) {
        const long m = m0 + wid * 32 + lid;
        float* Crow = C + bz * sC + m * ldc + n0;
#pragma unroll 1
        for (int b4 = 0; b4 < 4; ++b4) {
            uint32_t r[32];
            TCGEN05_LD_X32(r, tmem + b4 * 32);
            TCGEN05_WAIT_LD();
#pragma unroll
            for (int j = 0; j < 32; j += 4) {
                float4 v;
                v.x = __uint_as_float(r[j + 0]);
                v.y = __uint_as_float(r[j + 1]);
                v.z = __uint_as_float(r[j + 2]);
                v.w = __uint_as_float(r[j + 3]);
                if (EPI == 1) {
                    const float* bb = bias + n0 + b4 * 32 + j;
                    v.x = tanhf(v.x + bb[0]);
                    v.y = tanhf(v.y + bb[1]);
                    v.z = tanhf(v.z + bb[2]);
                    v.w = tanhf(v.w + bb[3]);
                }
                *(float4*)(Crow + b4 * 32 + j) = v;
            }
        }
    }
    __syncthreads();
    if (wid == 0) {
        TCGEN05_RELINQ();
        TCGEN05_DEALLOC(tmem, 128);
    }

#else  // ---------------- fp32 FFMA fallback (non-"a" pass) ----------------
    float (*As)[132] = (float(*)[132])smem;
    float (*Bs)[132] = (float(*)[132])(smem + 16 * 132 * 4);
    const int tx = tid & 15, ty = tid >> 4;
    const int K = K64 << 6;

    float acc[8][8];
#pragma unroll
    for (int i = 0; i < 8; i++)
#pragma unroll
        for (int j = 0; j < 8; j++) acc[i][j] = 0.0f;

    const int arow = tid >> 2, ac4 = (tid & 3) * 4;
#pragma unroll
    for (int seg = 0; seg < NSEG; ++seg) {
        const float* A = (seg == 0 ? A0 : A1) + bz * sA + m0 * lda;
        const float* B = (seg == 0 ? B0 : B1) + bz * sB + n0 * ldb;
        for (int kt = 0; kt < K; kt += 16) {
#pragma unroll
            for (int rr = 0; rr < 2; ++rr) {
                const int row = arow + rr * 64;
                float4 va = *(const float4*)(A + (long)row * lda + kt + ac4);
                As[ac4 + 0][row] = va.x; As[ac4 + 1][row] = va.y;
                As[ac4 + 2][row] = va.z; As[ac4 + 3][row] = va.w;
                float4 vb = *(const float4*)(B + (long)row * ldb + kt + ac4);
                Bs[ac4 + 0][row] = vb.x; Bs[ac4 + 1][row] = vb.y;
                Bs[ac4 + 2][row] = vb.z; Bs[ac4 + 3][row] = vb.w;
            }
            __syncthreads();
#pragma unroll
            for (int kk = 0; kk < 16; ++kk) {
                float a[8], b[8];
                *(float4*)&a[0] = *(const float4*)&As[kk][ty * 8];
                *(float4*)&a[4] = *(const float4*)&As[kk][ty * 8 + 4];
                *(float4*)&b[0] = *(const float4*)&Bs[kk][tx * 8];
                *(float4*)&b[4] = *(const float4*)&Bs[kk][tx * 8 + 4];
#pragma unroll
                for (int i = 0; i < 8; i++)
#pragma unroll
                    for (int j = 0; j < 8; j++)
                        acc[i][j] = fmaf(a[i], b[j], acc[i][j]);
            }
            __syncthreads();
        }
    }
    float* Cp = C + bz * sC + (m0 + ty * 8) * ldc + n0 + tx * 8;
#pragma unroll
    for (int i = 0; i < 8; i++) {
#pragma unroll
        for (int j = 0; j < 8; j += 4) {
            float4 v;
            v.x = acc[i][j + 0]; v.y = acc[i][j + 1];
            v.z = acc[i][j + 2]; v.w = acc[i][j + 3];
            if (EPI == 1) {
                const long nb = n0 + tx * 8 + j;
                v.x = tanhf(v.x + bias[nb + 0]);
                v.y = tanhf(v.y + bias[nb + 1]);
                v.z = tanhf(v.z + bias[nb + 2]);
                v.w = tanhf(v.w + bias[nb + 3]);
            }
            *(float4*)(Cp + (long)i * ldc + j) = v;
        }
    }
#endif
}

// ---------------- softmax over S=1024 (with ==0 -> -inf fill) ----------------
__global__ void softmax_kernel(float* __restrict__ S)
{
    const long row = blockIdx.x;
    float* p = S + (row << 10);
    const int tid = threadIdx.x;

    float v[4];
    float mx = -INFINITY;
#pragma unroll
    for (int i = 0; i < 4; i++) {
        float x = p[tid + (i << 8)];
        if (x == 0.0f) x = -INFINITY;
        v[i] = x;
        mx = fmaxf(mx, x);
    }
    __shared__ float red[8];
#pragma unroll
    for (int o = 16; o; o >>= 1) mx = fmaxf(mx, __shfl_xor_sync(0xffffffffu, mx, o));
    if ((tid & 31) == 0) red[tid >> 5] = mx;
    __syncthreads();
    const float m = fmaxf(fmaxf(fmaxf(red[0], red[1]), fmaxf(red[2], red[3])),
                          fmaxf(fmaxf(red[4], red[5]), fmaxf(red[6], red[7])));
    __syncthreads();
    float s = 0.0f;
#pragma unroll
    for (int i = 0; i < 4; i++) { v[i] = expf(v[i] - m); s += v[i]; }
#pragma unroll
    for (int o = 16; o; o >>= 1) s += __shfl_xor_sync(0xffffffffu, s, o);
    if ((tid & 31) == 0) red[tid >> 5] = s;
    __syncthreads();
    const float inv = 1.0f / (red[0] + red[1] + red[2] + red[3] +
                              red[4] + red[5] + red[6] + red[7]);
#pragma unroll
    for (int i = 0; i < 4; i++) p[tid + (i << 8)] = v[i] * inv;
}

// ---------------- enc [S,B,H] -> encT [b][h][s] (fp32 tiled transpose) ----------------
__global__ void transpose_enc(const float* __restrict__ enc, float* __restrict__ encT)
{
    __shared__ float t[32][33];
    const int b  = blockIdx.z;
    const int s0 = blockIdx.x << 5;
    const int h0 = blockIdx.y << 5;
    const int tx = threadIdx.x, ty = threadIdx.y;  // 32x8
#pragma unroll
    for (int j = 0; j < 4; ++j) {
        const int s = s0 + ty + j * 8;
        t[ty + j * 8][tx] = enc[(long)s * 32768 + b * 1024 + h0 + tx];
    }
    __syncthreads();
#pragma unroll
    for (int j = 0; j < 4; ++j) {
        const int h = h0 + ty + j * 8;
        encT[((long)b << 20) + ((long)h << 10) + s0 + tx] = t[tx][ty + j * 8];
    }
}

// ---------------- launch ----------------
extern "C" void kernel_launch(void* const* d_in, const int* in_sizes, int n_in,
                              void* d_out, int out_size)
{
    const float* query = (const float*)d_in[0];  // [B,T,H]
    const float* enc   = (const float*)d_in[1];  // [S,B,H]
    const float* W_in  = (const float*)d_in[3];  // [H,H]
    const float* W_out = (const float*)d_in[4];  // [H,2H]
    const float* b_out = (const float*)d_in[5];  // [H]
    float* out = (float*)d_out;                  // [B,T,H]

    float *Z, *S, *Cc, *encT;
    cudaGetSymbolAddress((void**)&Z, g_Z);
    cudaGetSymbolAddress((void**)&S, g_S);
    cudaGetSymbolAddress((void**)&Cc, g_C);
    cudaGetSymbolAddress((void**)&encT, g_encT);

    // single-stage SMEM: 2 CTAs/SM fit (split-3: 2x97KB, split-2: 2x65KB)
    const int SM3 = 1024 + 6 * 16384;  // 99,328 B
    const int SM2 = 1024 + 4 * 16384;  // 66,560 B
    cudaFuncSetAttribute(mma_gemm<3, 1, 0>, cudaFuncAttributeMaxDynamicSharedMemorySize, SM3);
    cudaFuncSetAttribute(mma_gemm<2, 1, 0>, cudaFuncAttributeMaxDynamicSharedMemorySize, SM2);
    cudaFuncSetAttribute(mma_gemm<2, 2, 1>, cudaFuncAttributeMaxDynamicSharedMemorySize, SM2);

    // encT for GEMM4 (independent of GEMMs 1-2; runs first)
    transpose_enc<<<dim3(32, 32, 32), dim3(32, 8)>>>(enc, encT);

    // 1) Z = Q @ W_in^T   [16384 x 1024], K=1024   (split-3: softmax-path precision)
    mma_gemm<3, 1, 0><<<dim3(8, 128, 1), 256, SM3>>>(
        query, W_in, nullptr, nullptr, 16, 1024, 1024, 0, 0, 0, Z, 1024, nullptr);

    // 2) scores[b] = Z[b] @ enc[:,b,:]^T   (batched; rows are s, k-contig in enc)
    mma_gemm<3, 1, 0><<<dim3(8, 4, 32), 256, SM3>>>(
        Z, enc, nullptr, nullptr, 16, 1024, 32768,
        512L * 1024, 1024, 512L * 1024, S, 1024, nullptr);

    // 3) softmax rows (with ==0 -> -inf quirk)
    softmax_kernel<<<16384, 256>>>(S);

    // 4) c[b] = P[b] @ encT[b]^T  (split-2 is enough post-softmax)
    mma_gemm<2, 1, 0><<<dim3(8, 4, 32), 256, SM2>>>(
        S, encT, nullptr, nullptr, 16, 1024, 1024,
        512L * 1024, 1024L * 1024, 512L * 1024, Cc, 1024, nullptr);

    // 5) out = tanh(C @ Wout1^T + Q @ Wout2^T + b)   (2 segments, K=2048 total)
    mma_gemm<2, 2, 1><<<dim3(8, 128, 1), 256, SM2>>>(
        Cc, W_out, query, W_out + 1024, 16, 1024, 2048, 0, 0, 0, out, 1024, b_out);
}

// round 15
// speedup vs baseline: 1.7970x; 1.3165x over previous
#include <cuda_runtime.h>
#include <cuda_bf16.h>
#include <cstdint>
#include <math.h>

// tcgen05 is only available in the arch-specific ("a") compilation pass.
#if defined(__CUDA_ARCH_FEAT_SM103_ALL) || defined(__CUDA_ARCH_FEAT_SM100_ALL) || \
    defined(__CUDA_ARCH_FEAT_SM110_ALL) || defined(__CUDA_ARCH_FEAT_SM101_ALL)
#define HAS_TCGEN05 1
#else
#define HAS_TCGEN05 0
#endif

// ---------------- scratch (allocation-free rule) ----------------
__device__ float g_Z[32L * 512 * 1024];      // 64MB
__device__ float g_S[32L * 512 * 1024];      // 64MB
__device__ float g_C[32L * 512 * 1024];      // 64MB
__device__ float g_encT[32L * 1024 * 1024];  // 128MB  [b][h][s]

#if HAS_TCGEN05
// ---------------- PTX helpers ----------------
__device__ __forceinline__ uint32_t smem_u32(const void* p) {
    uint32_t a;
    asm("{ .reg .u64 t; cvta.to.shared.u64 t, %1; cvt.u32.u64 %0, t; }" : "=r"(a) : "l"(p));
    return a;
}
__device__ __forceinline__ uint32_t elect_one() {
    uint32_t pred;
    asm volatile("{\n\t.reg .pred p;\n\telect.sync _|p, 0xFFFFFFFF;\n\tselp.b32 %0, 1, 0, p;\n\t}"
                 : "=r"(pred));
    return pred;
}

#define MBARRIER_INIT(addr, cnt) \
    asm volatile("mbarrier.init.shared.b64 [%0], %1;" :: "r"(addr), "r"(cnt) : "memory")

#define MBARRIER_WAIT_PARITY(mbar_smem_addr, phase_parity) do { \
    uint32_t _mbar = (uint32_t)(mbar_smem_addr); \
    uint32_t _parity = (uint32_t)(phase_parity); \
    uint32_t _done; \
    asm volatile( \
        "{\n\t.reg .pred p;\n\t" \
        "mbarrier.try_wait.parity.acquire.cta.shared::cta.b64 p, [%1], %2;\n\t" \
        "selp.b32 %0, 1, 0, p;\n\t}" \
        : "=r"(_done) : "r"(_mbar), "r"(_parity) : "memory"); \
    if (!_done) { \
        asm volatile( \
            "{\n\t.reg .pred P1;\n\t" \
            "WAIT_LOOP_%=:\n\t" \
            "mbarrier.try_wait.parity.acquire.cta.shared::cta.b64 P1, [%0], %1, 0x989680;\n\t" \
            "@P1 bra.uni WAIT_DONE_%=;\n\t" \
            "bra.uni WAIT_LOOP_%=;\n\t" \
            "WAIT_DONE_%=:\n\t}" \
            :: "r"(_mbar), "r"(_parity) : "memory"); \
    } \
} while (0)

#define TCGEN05_ALLOC(smem_addr, n) \
    asm volatile("tcgen05.alloc.cta_group::1.sync.aligned.shared::cta.b32 [%0], %1;" \
                 :: "r"((uint32_t)(smem_addr)), "r"((uint32_t)(n)) : "memory")
#define TCGEN05_DEALLOC(tm, n) \
    asm volatile("tcgen05.dealloc.cta_group::1.sync.aligned.b32 %0, %1;" :: "r"(tm), "r"((uint32_t)(n)))
#define TCGEN05_RELINQ() \
    asm volatile("tcgen05.relinquish_alloc_permit.cta_group::1.sync.aligned;")
#define TCGEN05_COMMIT(mb) \
    asm volatile("tcgen05.commit.cta_group::1.mbarrier::arrive::one.shared::cluster.b64 [%0];" \
                 :: "r"((uint32_t)(mb)) : "memory")
#define TCGEN05_FENCE_AFTER() asm volatile("tcgen05.fence::after_thread_sync;" ::: "memory")
#define TCGEN05_WAIT_LD()     asm volatile("tcgen05.wait::ld.sync.aligned;" ::: "memory")
#define FENCE_PROXY_ASYNC()   asm volatile("fence.proxy.async.shared::cta;" ::: "memory")

#define TCGEN05_LD_X32(r, tm) \
    asm volatile( \
        "tcgen05.ld.sync.aligned.32x32b.x32.b32 " \
        "{%0, %1, %2, %3, %4, %5, %6, %7, %8, %9, %10, %11, %12, %13, %14, %15, " \
        " %16, %17, %18, %19, %20, %21, %22, %23, %24, %25, %26, %27, %28, %29, %30, %31}, [%32];" \
        : "=r"((r)[0]),  "=r"((r)[1]),  "=r"((r)[2]),  "=r"((r)[3]), \
          "=r"((r)[4]),  "=r"((r)[5]),  "=r"((r)[6]),  "=r"((r)[7]), \
          "=r"((r)[8]),  "=r"((r)[9]),  "=r"((r)[10]), "=r"((r)[11]), \
          "=r"((r)[12]), "=r"((r)[13]), "=r"((r)[14]), "=r"((r)[15]), \
          "=r"((r)[16]), "=r"((r)[17]), "=r"((r)[18]), "=r"((r)[19]), \
          "=r"((r)[20]), "=r"((r)[21]), "=r"((r)[22]), "=r"((r)[23]), \
          "=r"((r)[24]), "=r"((r)[25]), "=r"((r)[26]), "=r"((r)[27]), \
          "=r"((r)[28]), "=r"((r)[29]), "=r"((r)[30]), "=r"((r)[31]) \
        : "r"(tm))

// SW128 SMEM descriptor (Blackwell): layout=2, version=1, SBO=64, LBO=1
static constexpr uint64_t DESC_BASE =
    (uint64_t(2) << 61) | (uint64_t(1) << 46) | (uint64_t(64) << 32) | (uint64_t(1) << 16);
__device__ __forceinline__ uint64_t make_desc(uint32_t addr) {
    return DESC_BASE | ((uint64_t)(addr >> 4) & 0x3FFF);
}

// cg1 SS bf16 MMA (f32 accum)
__device__ __forceinline__ void mma_ss(uint32_t d, uint64_t ad, uint64_t bd,
                                       uint32_t idesc, bool acc) {
    uint32_t e = acc ? 1u : 0u;
    asm volatile(
        "{\n\t.reg .pred p;\n\tsetp.ne.u32 p, %4, 0;\n\t"
        "tcgen05.mma.cta_group::1.kind::f16 [%0], %1, %2, %3, {%5, %5, %5, %5}, p;\n\t}"
        :: "r"(d), "l"(ad), "l"(bd), "r"(idesc), "r"(e), "r"(0u) : "memory");
}

// idesc: dtype=F32, a=BF16, b=BF16, N=128, M=128 (K-major both)
static constexpr uint32_t IDESC = (1u << 4) | (1u << 7) | (1u << 10) | (16u << 17) | (8u << 24);

// pack high 16 bits of two fp32 into one bf16x2 word (truncation split)
__device__ __forceinline__ uint32_t prmt_hi(uint32_t a, uint32_t b) {
    uint32_t r;
    asm("prmt.b32 %0, %1, %2, 0x7632;" : "=r"(r) : "r"(a), "r"(b));
    return r;
}

// ---------------- tile loader: fp32 -> NSPLIT bf16 planes via truncation split ----------------
// tile = 128 rows x 64 cols; SW128 layout; planes spaced 16KB apart starting at s0.
template <int NSPLIT>
__device__ __forceinline__ void load_tile(char* s0, const float* __restrict__ g,
                                          long ld, int tid) {
    const int grp = tid >> 3;     // 0..31 (row group)
    const int c8  = tid & 7;      // 8 fp32 elements each
#pragma unroll
    for (int p = 0; p < 4; ++p) {
        const int r = grp + (p << 5);
        const float* src = g + (long)r * ld + (c8 << 3);
        const float4 v0 = *(const float4*)(src);
        const float4 v1 = *(const float4*)(src + 4);
        const float x[8] = {v0.x, v0.y, v0.z, v0.w, v1.x, v1.y, v1.z, v1.w};
        uint32_t w0[4], w1[4], w2[4];
#pragma unroll
        for (int j = 0; j < 4; ++j) {
            const float a = x[2 * j], b = x[2 * j + 1];
            const uint32_t ua = __float_as_uint(a), ub = __float_as_uint(b);
            w0[j] = prmt_hi(ua, ub);
            const float ma = a - __uint_as_float(ua & 0xFFFF0000u);
            const float mb = b - __uint_as_float(ub & 0xFFFF0000u);
            const uint32_t uma = __float_as_uint(ma), umb = __float_as_uint(mb);
            w1[j] = prmt_hi(uma, umb);
            if (NSPLIT == 3) {
                const float la = ma - __uint_as_float(uma & 0xFFFF0000u);
                const float lb = mb - __uint_as_float(umb & 0xFFFF0000u);
                w2[j] = prmt_hi(__float_as_uint(la), __float_as_uint(lb));
            }
        }
        const uint32_t bo = (r << 7) + (c8 << 4);
        const uint32_t sw = bo ^ ((bo >> 3) & 0x70);
        *(uint4*)(s0 + sw)         = make_uint4(w0[0], w0[1], w0[2], w0[3]);
        *(uint4*)(s0 + 16384 + sw) = make_uint4(w1[0], w1[1], w1[2], w1[3]);
        if (NSPLIT == 3)
            *(uint4*)(s0 + 32768 + sw) = make_uint4(w2[0], w2[1], w2[2], w2[3]);
    }
}
#endif  // HAS_TCGEN05

// ---------------- main GEMM ----------------
// C[bz][m,n] (+= over NSEG segs) = sum_k A[m,k] * B[n,k]  (both operands K-contiguous)
// EPI: 0 = fp32 store, 1 = tanh(x + bias[n]) store.
// Double-buffered stages (R4-proven structure); truncation split in the loader.
template <int NSPLIT, int NSEG, int EPI>
__global__ void __launch_bounds__(256, 1)
mma_gemm(const float* A0, const float* B0, const float* A1, const float* B1,
         int K64, long lda, long ldb, long sA, long sB, long sC,
         float* __restrict__ C, int ldc, const float* __restrict__ bias)
{
    extern __shared__ char smem[];
    const int tid = threadIdx.x;
    const long m0 = (long)blockIdx.y * 128;
    const long n0 = (long)blockIdx.x * 128;
    const long bz = blockIdx.z;

#if HAS_TCGEN05
    constexpr int ARR   = 16384;
    constexpr int STAGE = NSPLIT * 2 * ARR;
    const uint32_t sb = smem_u32(smem);
    const int wid = tid >> 5, lid = tid & 31;

    if (wid == 0) TCGEN05_ALLOC(sb, 128);
    __syncthreads();
    uint32_t tmem;
    asm volatile("ld.shared.b32 %0, [%1];" : "=r"(tmem) : "r"(sb));
    if (tid == 0) { MBARRIER_INIT(sb + 8, 1); MBARRIER_INIT(sb + 16, 1); }
    __syncthreads();

    const int total = NSEG * K64;
    int ph0 = 0, ph1 = 0;

    // prologue: load chunk 0 into stage 0
    {
        char* st = smem + 1024;
        load_tile<NSPLIT>(st, A0 + bz * sA + m0 * lda, lda, tid);
        load_tile<NSPLIT>(st + NSPLIT * ARR, B0 + bz * sB + n0 * ldb, ldb, tid);
        FENCE_PROXY_ASYNC();
        __syncthreads();
    }

#pragma unroll 1
    for (int c = 0; c < total; ++c) {
        const int s = c & 1;
        if (wid == 0) {
            if (elect_one()) {
                const uint32_t stb = sb + 1024 + s * STAGE;
                uint64_t dA[3], dB[3];
#pragma unroll
                for (int i = 0; i < NSPLIT; ++i) {
                    dA[i] = make_desc(stb + i * ARR);
                    dB[i] = make_desc(stb + (NSPLIT + i) * ARR);
                }
#pragma unroll
                for (int k = 0; k < 4; ++k) {
                    const uint64_t off = (uint64_t)(k * 2);
                    const bool first = (c == 0) && (k == 0);
                    if (NSPLIT == 3) {
                        mma_ss(tmem, dA[2] + off, dB[0] + off, IDESC, !first);
                        mma_ss(tmem, dA[0] + off, dB[2] + off, IDESC, true);
                        mma_ss(tmem, dA[1] + off, dB[1] + off, IDESC, true);
                        mma_ss(tmem, dA[1] + off, dB[0] + off, IDESC, true);
                        mma_ss(tmem, dA[0] + off, dB[1] + off, IDESC, true);
                        mma_ss(tmem, dA[0] + off, dB[0] + off, IDESC, true);
                    } else {
                        mma_ss(tmem, dA[1] + off, dB[0] + off, IDESC, !first);
                        mma_ss(tmem, dA[0] + off, dB[1] + off, IDESC, true);
                        mma_ss(tmem, dA[0] + off, dB[0] + off, IDESC, true);
                    }
                }
                TCGEN05_COMMIT(sb + 8 + s * 8);
            }
        }
        // load next chunk into the other stage while MMAs run
        if (c + 1 < total) {
            const int s2 = (c + 1) & 1;
            if (c + 1 >= 2) {
                if (s2 == 0) { MBARRIER_WAIT_PARITY(sb + 8, ph0); ph0 ^= 1; }
                else         { MBARRIER_WAIT_PARITY(sb + 16, ph1); ph1 ^= 1; }
            }
            const int cn = c + 1;
            const int seg = (NSEG == 2) ? (int)(cn >= K64) : 0;
            const long kt = (long)(cn - seg * K64) << 6;
            const float* Ag = (seg ? A1 : A0) + bz * sA + m0 * lda + kt;
            const float* Bg = (seg ? B1 : B0) + bz * sB + n0 * ldb + kt;
            char* st = smem + 1024 + s2 * STAGE;
            load_tile<NSPLIT>(st, Ag, lda, tid);
            load_tile<NSPLIT>(st + NSPLIT * ARR, Bg, ldb, tid);
            FENCE_PROXY_ASYNC();
            __syncthreads();
        }
    }

    // wait for last chunk's MMAs
    {
        const int sl = (total - 1) & 1;
        if (sl == 0) { MBARRIER_WAIT_PARITY(sb + 8, ph0); }
        else         { MBARRIER_WAIT_PARITY(sb + 16, ph1); }
    }
    TCGEN05_FENCE_AFTER();

    if (wid < 4) {
        const long m = m0 + wid * 32 + lid;
        float* Crow = C + bz * sC + m * ldc + n0;
#pragma unroll 1
        for (int b4 = 0; b4 < 4; ++b4) {
            uint32_t r[32];
            TCGEN05_LD_X32(r, tmem + b4 * 32);
            TCGEN05_WAIT_LD();
#pragma unroll
            for (int j = 0; j < 32; j += 4) {
                float4 v;
                v.x = __uint_as_float(r[j + 0]);
                v.y = __uint_as_float(r[j + 1]);
                v.z = __uint_as_float(r[j + 2]);
                v.w = __uint_as_float(r[j + 3]);
                if (EPI == 1) {
                    const float* bb = bias + n0 + b4 * 32 + j;
                    v.x = tanhf(v.x + bb[0]);
                    v.y = tanhf(v.y + bb[1]);
                    v.z = tanhf(v.z + bb[2]);
                    v.w = tanhf(v.w + bb[3]);
                }
                *(float4*)(Crow + b4 * 32 + j) = v;
            }
        }
    }
    __syncthreads();
    if (wid == 0) {
        TCGEN05_RELINQ();
        TCGEN05_DEALLOC(tmem, 128);
    }

#else  // ---------------- fp32 FFMA fallback (non-"a" pass) ----------------
    float (*As)[132] = (float(*)[132])smem;
    float (*Bs)[132] = (float(*)[132])(smem + 16 * 132 * 4);
    const int tx = tid & 15, ty = tid >> 4;
    const int K = K64 << 6;

    float acc[8][8];
#pragma unroll
    for (int i = 0; i < 8; i++)
#pragma unroll
        for (int j = 0; j < 8; j++) acc[i][j] = 0.0f;

    const int arow = tid >> 2, ac4 = (tid & 3) * 4;
#pragma unroll
    for (int seg = 0; seg < NSEG; ++seg) {
        const float* A = (seg == 0 ? A0 : A1) + bz * sA + m0 * lda;
        const float* B = (seg == 0 ? B0 : B1) + bz * sB + n0 * ldb;
        for (int kt = 0; kt < K; kt += 16) {
#pragma unroll
            for (int rr = 0; rr < 2; ++rr) {
                const int row = arow + rr * 64;
                float4 va = *(const float4*)(A + (long)row * lda + kt + ac4);
                As[ac4 + 0][row] = va.x; As[ac4 + 1][row] = va.y;
                As[ac4 + 2][row] = va.z; As[ac4 + 3][row] = va.w;
                float4 vb = *(const float4*)(B + (long)row * ldb + kt + ac4);
                Bs[ac4 + 0][row] = vb.x; Bs[ac4 + 1][row] = vb.y;
                Bs[ac4 + 2][row] = vb.z; Bs[ac4 + 3][row] = vb.w;
            }
            __syncthreads();
#pragma unroll
            for (int kk = 0; kk < 16; ++kk) {
                float a[8], b[8];
                *(float4*)&a[0] = *(const float4*)&As[kk][ty * 8];
                *(float4*)&a[4] = *(const float4*)&As[kk][ty * 8 + 4];
                *(float4*)&b[0] = *(const float4*)&Bs[kk][tx * 8];
                *(float4*)&b[4] = *(const float4*)&Bs[kk][tx * 8 + 4];
#pragma unroll
                for (int i = 0; i < 8; i++)
#pragma unroll
                    for (int j = 0; j < 8; j++)
                        acc[i][j] = fmaf(a[i], b[j], acc[i][j]);
            }
            __syncthreads();
        }
    }
    float* Cp = C + bz * sC + (m0 + ty * 8) * ldc + n0 + tx * 8;
#pragma unroll
    for (int i = 0; i < 8; i++) {
#pragma unroll
        for (int j = 0; j < 8; j += 4) {
            float4 v;
            v.x = acc[i][j + 0]; v.y = acc[i][j + 1];
            v.z = acc[i][j + 2]; v.w = acc[i][j + 3];
            if (EPI == 1) {
                const long nb = n0 + tx * 8 + j;
                v.x = tanhf(v.x + bias[nb + 0]);
                v.y = tanhf(v.y + bias[nb + 1]);
                v.z = tanhf(v.z + bias[nb + 2]);
                v.w = tanhf(v.w + bias[nb + 3]);
            }
            *(float4*)(Cp + (long)i * ldc + j) = v;
        }
    }
#endif
}

// ---------------- softmax over S=1024 (with ==0 -> -inf fill) ----------------
__global__ void softmax_kernel(float* __restrict__ S)
{
    const long row = blockIdx.x;
    float* p = S + (row << 10);
    const int tid = threadIdx.x;

    float v[4];
    float mx = -INFINITY;
#pragma unroll
    for (int i = 0; i < 4; i++) {
        float x = p[tid + (i << 8)];
        if (x == 0.0f) x = -INFINITY;
        v[i] = x;
        mx = fmaxf(mx, x);
    }
    __shared__ float red[8];
#pragma unroll
    for (int o = 16; o; o >>= 1) mx = fmaxf(mx, __shfl_xor_sync(0xffffffffu, mx, o));
    if ((tid & 31) == 0) red[tid >> 5] = mx;
    __syncthreads();
    const float m = fmaxf(fmaxf(fmaxf(red[0], red[1]), fmaxf(red[2], red[3])),
                          fmaxf(fmaxf(red[4], red[5]), fmaxf(red[6], red[7])));
    __syncthreads();
    float s = 0.0f;
#pragma unroll
    for (int i = 0; i < 4; i++) { v[i] = expf(v[i] - m); s += v[i]; }
#pragma unroll
    for (int o = 16; o; o >>= 1) s += __shfl_xor_sync(0xffffffffu, s, o);
    if ((tid & 31) == 0) red[tid >> 5] = s;
    __syncthreads();
    const float inv = 1.0f / (red[0] + red[1] + red[2] + red[3] +
                              red[4] + red[5] + red[6] + red[7]);
#pragma unroll
    for (int i = 0; i < 4; i++) p[tid + (i << 8)] = v[i] * inv;
}

// ---------------- enc [S,B,H] -> encT [b][h][s] (fp32 tiled transpose) ----------------
__global__ void transpose_enc(const float* __restrict__ enc, float* __restrict__ encT)
{
    __shared__ float t[32][33];
    const int b  = blockIdx.z;
    const int s0 = blockIdx.x << 5;
    const int h0 = blockIdx.y << 5;
    const int tx = threadIdx.x, ty = threadIdx.y;  // 32x8
#pragma unroll
    for (int j = 0; j < 4; ++j) {
        const int s = s0 + ty + j * 8;
        t[ty + j * 8][tx] = enc[(long)s * 32768 + b * 1024 + h0 + tx];
    }
    __syncthreads();
#pragma unroll
    for (int j = 0; j < 4; ++j) {
        const int h = h0 + ty + j * 8;
        encT[((long)b << 20) + ((long)h << 10) + s0 + tx] = t[tx][ty + j * 8];
    }
}

// ---------------- launch ----------------
extern "C" void kernel_launch(void* const* d_in, const int* in_sizes, int n_in,
                              void* d_out, int out_size)
{
    const float* query = (const float*)d_in[0];  // [B,T,H]
    const float* enc   = (const float*)d_in[1];  // [S,B,H]
    const float* W_in  = (const float*)d_in[3];  // [H,H]
    const float* W_out = (const float*)d_in[4];  // [H,2H]
    const float* b_out = (const float*)d_in[5];  // [H]
    float* out = (float*)d_out;                  // [B,T,H]

    float *Z, *S, *Cc, *encT;
    cudaGetSymbolAddress((void**)&Z, g_Z);
    cudaGetSymbolAddress((void**)&S, g_S);
    cudaGetSymbolAddress((void**)&Cc, g_C);
    cudaGetSymbolAddress((void**)&encT, g_encT);

    const int SM3 = 1024 + 2 * 6 * 16384;  // 197,632 B
    const int SM2 = 1024 + 2 * 4 * 16384;  // 132,096 B
    cudaFuncSetAttribute(mma_gemm<3, 1, 0>, cudaFuncAttributeMaxDynamicSharedMemorySize, SM3);
    cudaFuncSetAttribute(mma_gemm<2, 1, 0>, cudaFuncAttributeMaxDynamicSharedMemorySize, SM2);
    cudaFuncSetAttribute(mma_gemm<2, 2, 1>, cudaFuncAttributeMaxDynamicSharedMemorySize, SM2);

    // encT for GEMM4 (independent of GEMMs 1-2; runs first)
    transpose_enc<<<dim3(32, 32, 32), dim3(32, 8)>>>(enc, encT);

    // 1) Z = Q @ W_in^T   [16384 x 1024], K=1024   (split-3: softmax-path precision)
    mma_gemm<3, 1, 0><<<dim3(8, 128, 1), 256, SM3>>>(
        query, W_in, nullptr, nullptr, 16, 1024, 1024, 0, 0, 0, Z, 1024, nullptr);

    // 2) scores[b] = Z[b] @ enc[:,b,:]^T   (batched; rows are s, k-contig in enc)
    mma_gemm<3, 1, 0><<<dim3(8, 4, 32), 256, SM3>>>(
        Z, enc, nullptr, nullptr, 16, 1024, 32768,
        512L * 1024, 1024, 512L * 1024, S, 1024, nullptr);

    // 3) softmax rows (with ==0 -> -inf quirk)
    softmax_kernel<<<16384, 256>>>(S);

    // 4) c[b] = P[b] @ encT[b]^T  (split-2 is enough post-softmax)
    mma_gemm<2, 1, 0><<<dim3(8, 4, 32), 256, SM2>>>(
        S, encT, nullptr, nullptr, 16, 1024, 1024,
        512L * 1024, 1024L * 1024, 512L * 1024, Cc, 1024, nullptr);

    // 5) out = tanh(C @ Wout1^T + Q @ Wout2^T + b)   (2 segments, K=2048 total)
    mma_gemm<2, 2, 1><<<dim3(8, 128, 1), 256, SM2>>>(
        Cc, W_out, query, W_out + 1024, 16, 1024, 2048, 0, 0, 0, out, 1024, b_out);
}

// round 16
// speedup vs baseline: 1.8855x; 1.0492x over previous
#include <cuda_runtime.h>
#include <cuda_bf16.h>
#include <cstdint>
#include <math.h>

// tcgen05 is only available in the arch-specific ("a") compilation pass.
#if defined(__CUDA_ARCH_FEAT_SM103_ALL) || defined(__CUDA_ARCH_FEAT_SM100_ALL) || \
    defined(__CUDA_ARCH_FEAT_SM110_ALL) || defined(__CUDA_ARCH_FEAT_SM101_ALL)
#define HAS_TCGEN05 1
#else
#define HAS_TCGEN05 0
#endif

// ---------------- scratch (allocation-free rule) ----------------
__device__ float g_Z[32L * 512 * 1024];      // 64MB
__device__ float g_S[32L * 512 * 1024];      // 64MB  raw scores
__device__ float g_C[32L * 512 * 1024];      // 64MB  context (fp32)
__device__ float g_encT[32L * 1024 * 1024];  // 128MB fallback encT

// plane-interleaved split tiles: tile block = NSPLIT x 16KB contiguous
__device__ uint4 g_wiP[128L * 3 * 1024];        // W_in  split-3: 8x16 tiles, 6MB
__device__ uint4 g_woP[256L * 2 * 1024];        // W_out split-2: 8x32 tiles, 8MB
__device__ uint4 g_pP [2048L * 2 * 1024];       // P     split-2: 128x16 tiles, 64MB
__device__ uint4 g_etP[4096L * 2 * 1024];       // encT  split-2: 32x8x16 tiles, 128MB

// ---------------- helpers usable in all passes ----------------
__device__ __forceinline__ uint32_t prmt_hi(uint32_t a, uint32_t b) {
    uint32_t r;
    asm("prmt.b32 %0, %1, %2, 0x7632;" : "=r"(r) : "r"(a), "r"(b));
    return r;
}

// tile loader: fp32 -> NSPLIT bf16 planes via truncation split.
// tile = 128 rows x 64 cols; SW128 layout; planes spaced 16KB apart at s0.
// s0 may be SMEM or GMEM (generic stores).
template <int NSPLIT>
__device__ __forceinline__ void load_tile(char* s0, const float* __restrict__ g,
                                          long ld, int tid) {
    const int grp = tid >> 3;     // 0..31 (row group)
    const int c8  = tid & 7;      // 8 fp32 elements each
#pragma unroll
    for (int p = 0; p < 4; ++p) {
        const int r = grp + (p << 5);
        const float* src = g + (long)r * ld + (c8 << 3);
        const float4 v0 = *(const float4*)(src);
        const float4 v1 = *(const float4*)(src + 4);
        const float x[8] = {v0.x, v0.y, v0.z, v0.w, v1.x, v1.y, v1.z, v1.w};
        uint32_t w0[4], w1[4], w2[4];
#pragma unroll
        for (int j = 0; j < 4; ++j) {
            const float a = x[2 * j], b = x[2 * j + 1];
            const uint32_t ua = __float_as_uint(a), ub = __float_as_uint(b);
            w0[j] = prmt_hi(ua, ub);
            const float ma = a - __uint_as_float(ua & 0xFFFF0000u);
            const float mb = b - __uint_as_float(ub & 0xFFFF0000u);
            const uint32_t uma = __float_as_uint(ma), umb = __float_as_uint(mb);
            w1[j] = prmt_hi(uma, umb);
            if (NSPLIT == 3) {
                const float la = ma - __uint_as_float(uma & 0xFFFF0000u);
                const float lb = mb - __uint_as_float(umb & 0xFFFF0000u);
                w2[j] = prmt_hi(__float_as_uint(la), __float_as_uint(lb));
            }
        }
        const uint32_t bo = (r << 7) + (c8 << 4);
        const uint32_t sw = bo ^ ((bo >> 3) & 0x70);
        *(uint4*)(s0 + sw)         = make_uint4(w0[0], w0[1], w0[2], w0[3]);
        *(uint4*)(s0 + 16384 + sw) = make_uint4(w1[0], w1[1], w1[2], w1[3]);
        if (NSPLIT == 3)
            *(uint4*)(s0 + 32768 + sw) = make_uint4(w2[0], w2[1], w2[2], w2[3]);
    }
}

// contiguous NBYTES copy, 256 threads, 16B-aligned both sides
template <int NBYTES>
__device__ __forceinline__ void copyN(char* dst, const char* __restrict__ src, int tid) {
    const uint4* s = (const uint4*)src;
    uint4* d = (uint4*)dst;
#pragma unroll
    for (int i = 0; i < NBYTES / 4096; ++i) d[tid + i * 256] = s[tid + i * 256];
}

// pre-split a weight matrix into plane-interleaved swizzled tiles
template <int NSPLIT>
__global__ void split_w(const float* __restrict__ src, long ld, char* __restrict__ dst)
{
    const long tOff = ((long)blockIdx.y * gridDim.x + blockIdx.x) * (NSPLIT * 16384L);
    const float* g = src + ((long)blockIdx.y * 128) * ld + blockIdx.x * 64;
    load_tile<NSPLIT>(dst + tOff, g, ld, threadIdx.x);
}

#if HAS_TCGEN05
// ---------------- PTX helpers ----------------
__device__ __forceinline__ uint32_t smem_u32(const void* p) {
    uint32_t a;
    asm("{ .reg .u64 t; cvta.to.shared.u64 t, %1; cvt.u32.u64 %0, t; }" : "=r"(a) : "l"(p));
    return a;
}
__device__ __forceinline__ uint32_t elect_one() {
    uint32_t pred;
    asm volatile("{\n\t.reg .pred p;\n\telect.sync _|p, 0xFFFFFFFF;\n\tselp.b32 %0, 1, 0, p;\n\t}"
                 : "=r"(pred));
    return pred;
}

#define MBARRIER_INIT(addr, cnt) \
    asm volatile("mbarrier.init.shared.b64 [%0], %1;" :: "r"(addr), "r"(cnt) : "memory")

#define MBARRIER_WAIT_PARITY(mbar_smem_addr, phase_parity) do { \
    uint32_t _mbar = (uint32_t)(mbar_smem_addr); \
    uint32_t _parity = (uint32_t)(phase_parity); \
    uint32_t _done; \
    asm volatile( \
        "{\n\t.reg .pred p;\n\t" \
        "mbarrier.try_wait.parity.acquire.cta.shared::cta.b64 p, [%1], %2;\n\t" \
        "selp.b32 %0, 1, 0, p;\n\t}" \
        : "=r"(_done) : "r"(_mbar), "r"(_parity) : "memory"); \
    if (!_done) { \
        asm volatile( \
            "{\n\t.reg .pred P1;\n\t" \
            "WAIT_LOOP_%=:\n\t" \
            "mbarrier.try_wait.parity.acquire.cta.shared::cta.b64 P1, [%0], %1, 0x989680;\n\t" \
            "@P1 bra.uni WAIT_DONE_%=;\n\t" \
            "bra.uni WAIT_LOOP_%=;\n\t" \
            "WAIT_DONE_%=:\n\t}" \
            :: "r"(_mbar), "r"(_parity) : "memory"); \
    } \
} while (0)

#define TCGEN05_ALLOC(smem_addr, n) \
    asm volatile("tcgen05.alloc.cta_group::1.sync.aligned.shared::cta.b32 [%0], %1;" \
                 :: "r"((uint32_t)(smem_addr)), "r"((uint32_t)(n)) : "memory")
#define TCGEN05_DEALLOC(tm, n) \
    asm volatile("tcgen05.dealloc.cta_group::1.sync.aligned.b32 %0, %1;" :: "r"(tm), "r"((uint32_t)(n)))
#define TCGEN05_RELINQ() \
    asm volatile("tcgen05.relinquish_alloc_permit.cta_group::1.sync.aligned;")
#define TCGEN05_COMMIT(mb) \
    asm volatile("tcgen05.commit.cta_group::1.mbarrier::arrive::one.shared::cluster.b64 [%0];" \
                 :: "r"((uint32_t)(mb)) : "memory")
#define TCGEN05_FENCE_AFTER() asm volatile("tcgen05.fence::after_thread_sync;" ::: "memory")
#define TCGEN05_WAIT_LD()     asm volatile("tcgen05.wait::ld.sync.aligned;" ::: "memory")
#define FENCE_PROXY_ASYNC()   asm volatile("fence.proxy.async.shared::cta;" ::: "memory")

#define TCGEN05_LD_X32(r, tm) \
    asm volatile( \
        "tcgen05.ld.sync.aligned.32x32b.x32.b32 " \
        "{%0, %1, %2, %3, %4, %5, %6, %7, %8, %9, %10, %11, %12, %13, %14, %15, " \
        " %16, %17, %18, %19, %20, %21, %22, %23, %24, %25, %26, %27, %28, %29, %30, %31}, [%32];" \
        : "=r"((r)[0]),  "=r"((r)[1]),  "=r"((r)[2]),  "=r"((r)[3]), \
          "=r"((r)[4]),  "=r"((r)[5]),  "=r"((r)[6]),  "=r"((r)[7]), \
          "=r"((r)[8]),  "=r"((r)[9]),  "=r"((r)[10]), "=r"((r)[11]), \
          "=r"((r)[12]), "=r"((r)[13]), "=r"((r)[14]), "=r"((r)[15]), \
          "=r"((r)[16]), "=r"((r)[17]), "=r"((r)[18]), "=r"((r)[19]), \
          "=r"((r)[20]), "=r"((r)[21]), "=r"((r)[22]), "=r"((r)[23]), \
          "=r"((r)[24]), "=r"((r)[25]), "=r"((r)[26]), "=r"((r)[27]), \
          "=r"((r)[28]), "=r"((r)[29]), "=r"((r)[30]), "=r"((r)[31]) \
        : "r"(tm))

// SW128 SMEM descriptor (Blackwell): layout=2, version=1, SBO=64, LBO=1
static constexpr uint64_t DESC_BASE =
    (uint64_t(2) << 61) | (uint64_t(1) << 46) | (uint64_t(64) << 32) | (uint64_t(1) << 16);
__device__ __forceinline__ uint64_t make_desc(uint32_t addr) {
    return DESC_BASE | ((uint64_t)(addr >> 4) & 0x3FFF);
}

// cg1 SS bf16 MMA (f32 accum)
__device__ __forceinline__ void mma_ss(uint32_t d, uint64_t ad, uint64_t bd,
                                       uint32_t idesc, bool acc) {
    uint32_t e = acc ? 1u : 0u;
    asm volatile(
        "{\n\t.reg .pred p;\n\tsetp.ne.u32 p, %4, 0;\n\t"
        "tcgen05.mma.cta_group::1.kind::f16 [%0], %1, %2, %3, {%5, %5, %5, %5}, p;\n\t}"
        :: "r"(d), "l"(ad), "l"(bd), "r"(idesc), "r"(e), "r"(0u) : "memory");
}

// idesc: dtype=F32, a=BF16, b=BF16, N=128, M=128 (K-major both)
static constexpr uint32_t IDESC = (1u << 4) | (1u << 7) | (1u << 10) | (16u << 17) | (8u << 24);
#endif  // HAS_TCGEN05

// ---------------- main GEMM ----------------
// C[bz][m,n] (+= over NSEG segs) = sum_k A[m,k] * B[n,k]
// APRE/BPRE: operand comes from pre-split plane-interleaved tiles (pure copy loader).
// EPI: 0 = fp32 store, 1 = tanh(x + bias[n]) store.
template <int NSPLIT, int NSEG, int EPI, int APRE, int BPRE>
__global__ void __launch_bounds__(256, 1)
mma_gemm(const float* A0, const float* B0, const float* A1, const float* B1,
         const char* aPl, const char* bPl,
         int K64, int mBPB, int nBPB,
         long lda, long ldb, long sA, long sB, long sC,
         float* __restrict__ C, int ldc, const float* __restrict__ bias)
{
    extern __shared__ char smem[];
    const int tid = threadIdx.x;
    const long m0 = (long)blockIdx.y * 128;
    const long n0 = (long)blockIdx.x * 128;
    const long bz = blockIdx.z;

#if HAS_TCGEN05
    constexpr int ARR   = 16384;
    constexpr int STAGE = NSPLIT * 2 * ARR;
    const uint32_t sb = smem_u32(smem);
    const int wid = tid >> 5, lid = tid & 31;
    const long aBlk = bz * mBPB + blockIdx.y;
    const long bBlk = bz * nBPB + blockIdx.x;
    const int K64T = NSEG * K64;

    if (wid == 0) TCGEN05_ALLOC(sb, 128);
    __syncthreads();
    uint32_t tmem;
    asm volatile("ld.shared.b32 %0, [%1];" : "=r"(tmem) : "r"(sb));
    if (tid == 0) { MBARRIER_INIT(sb + 8, 1); MBARRIER_INIT(sb + 16, 1); }
    __syncthreads();

    int ph0 = 0, ph1 = 0;

    auto load_chunk = [&](int c, char* st) {
        if (APRE) {
            copyN<NSPLIT * 16384>(st, aPl + (aBlk * K64T + c) * (NSPLIT * 16384L), tid);
        } else {
            const int seg = (NSEG == 2) ? (int)(c >= K64) : 0;
            const long kt = (long)(c - seg * K64) << 6;
            const float* Ag = (seg ? A1 : A0) + bz * sA + m0 * lda + kt;
            load_tile<NSPLIT>(st, Ag, lda, tid);
        }
        if (BPRE) {
            copyN<NSPLIT * 16384>(st + NSPLIT * ARR,
                                  bPl + (bBlk * K64T + c) * (NSPLIT * 16384L), tid);
        } else {
            const int seg = (NSEG == 2) ? (int)(c >= K64) : 0;
            const long kt = (long)(c - seg * K64) << 6;
            const float* Bg = (seg ? B1 : B0) + bz * sB + n0 * ldb + kt;
            load_tile<NSPLIT>(st + NSPLIT * ARR, Bg, ldb, tid);
        }
    };

    load_chunk(0, smem + 1024);
    FENCE_PROXY_ASYNC();
    __syncthreads();

#pragma unroll 1
    for (int c = 0; c < K64T; ++c) {
        const int s = c & 1;
        if (wid == 0) {
            if (elect_one()) {
                const uint32_t stb = sb + 1024 + s * STAGE;
                uint64_t dA[3], dB[3];
#pragma unroll
                for (int i = 0; i < NSPLIT; ++i) {
                    dA[i] = make_desc(stb + i * ARR);
                    dB[i] = make_desc(stb + (NSPLIT + i) * ARR);
                }
#pragma unroll
                for (int k = 0; k < 4; ++k) {
                    const uint64_t off = (uint64_t)(k * 2);
                    const bool first = (c == 0) && (k == 0);
                    if (NSPLIT == 3) {
                        mma_ss(tmem, dA[2] + off, dB[0] + off, IDESC, !first);
                        mma_ss(tmem, dA[0] + off, dB[2] + off, IDESC, true);
                        mma_ss(tmem, dA[1] + off, dB[1] + off, IDESC, true);
                        mma_ss(tmem, dA[1] + off, dB[0] + off, IDESC, true);
                        mma_ss(tmem, dA[0] + off, dB[1] + off, IDESC, true);
                        mma_ss(tmem, dA[0] + off, dB[0] + off, IDESC, true);
                    } else {
                        mma_ss(tmem, dA[1] + off, dB[0] + off, IDESC, !first);
                        mma_ss(tmem, dA[0] + off, dB[1] + off, IDESC, true);
                        mma_ss(tmem, dA[0] + off, dB[0] + off, IDESC, true);
                    }
                }
                TCGEN05_COMMIT(sb + 8 + s * 8);
            }
        }
        if (c + 1 < K64T) {
            const int s2 = (c + 1) & 1;
            if (c + 1 >= 2) {
                if (s2 == 0) { MBARRIER_WAIT_PARITY(sb + 8, ph0); ph0 ^= 1; }
                else         { MBARRIER_WAIT_PARITY(sb + 16, ph1); ph1 ^= 1; }
            }
            load_chunk(c + 1, smem + 1024 + s2 * STAGE);
            FENCE_PROXY_ASYNC();
            __syncthreads();
        }
    }

    {
        const int sl = (K64T - 1) & 1;
        if (sl == 0) { MBARRIER_WAIT_PARITY(sb + 8, ph0); }
        else         { MBARRIER_WAIT_PARITY(sb + 16, ph1); }
    }
    TCGEN05_FENCE_AFTER();

    if (wid < 4) {
        const long m = m0 + wid * 32 + lid;
        float* Crow = C + bz * sC + m * ldc + n0;
#pragma unroll 1
        for (int b4 = 0; b4 < 4; ++b4) {
            uint32_t r[32];
            TCGEN05_LD_X32(r, tmem + b4 * 32);
            TCGEN05_WAIT_LD();
#pragma unroll
            for (int j = 0; j < 32; j += 4) {
                float4 v;
                v.x = __uint_as_float(r[j + 0]);
                v.y = __uint_as_float(r[j + 1]);
                v.z = __uint_as_float(r[j + 2]);
                v.w = __uint_as_float(r[j + 3]);
                if (EPI == 1) {
                    const float* bb = bias + n0 + b4 * 32 + j;
                    v.x = tanhf(v.x + bb[0]);
                    v.y = tanhf(v.y + bb[1]);
                    v.z = tanhf(v.z + bb[2]);
                    v.w = tanhf(v.w + bb[3]);
                }
                *(float4*)(Crow + b4 * 32 + j) = v;
            }
        }
    }
    __syncthreads();
    if (wid == 0) {
        TCGEN05_RELINQ();
        TCGEN05_DEALLOC(tmem, 128);
    }

#else  // ---------------- fp32 FFMA fallback (non-"a" pass) ----------------
    float (*As)[132] = (float(*)[132])smem;
    float (*Bs)[132] = (float(*)[132])(smem + 16 * 132 * 4);
    const int tx = tid & 15, ty = tid >> 4;
    const int K = K64 << 6;

    float acc[8][8];
#pragma unroll
    for (int i = 0; i < 8; i++)
#pragma unroll
        for (int j = 0; j < 8; j++) acc[i][j] = 0.0f;

    const int arow = tid >> 2, ac4 = (tid & 3) * 4;
#pragma unroll
    for (int seg = 0; seg < NSEG; ++seg) {
        const float* A = (seg == 0 ? A0 : A1) + bz * sA + m0 * lda;
        const float* B = (seg == 0 ? B0 : B1) + bz * sB + n0 * ldb;
        for (int kt = 0; kt < K; kt += 16) {
#pragma unroll
            for (int rr = 0; rr < 2; ++rr) {
                const int row = arow + rr * 64;
                float4 va = *(const float4*)(A + (long)row * lda + kt + ac4);
                As[ac4 + 0][row] = va.x; As[ac4 + 1][row] = va.y;
                As[ac4 + 2][row] = va.z; As[ac4 + 3][row] = va.w;
                float4 vb = *(const float4*)(B + (long)row * ldb + kt + ac4);
                Bs[ac4 + 0][row] = vb.x; Bs[ac4 + 1][row] = vb.y;
                Bs[ac4 + 2][row] = vb.z; Bs[ac4 + 3][row] = vb.w;
            }
            __syncthreads();
#pragma unroll
            for (int kk = 0; kk < 16; ++kk) {
                float a[8], b[8];
                *(float4*)&a[0] = *(const float4*)&As[kk][ty * 8];
                *(float4*)&a[4] = *(const float4*)&As[kk][ty * 8 + 4];
                *(float4*)&b[0] = *(const float4*)&Bs[kk][tx * 8];
                *(float4*)&b[4] = *(const float4*)&Bs[kk][tx * 8 + 4];
#pragma unroll
                for (int i = 0; i < 8; i++)
#pragma unroll
                    for (int j = 0; j < 8; j++)
                        acc[i][j] = fmaf(a[i], b[j], acc[i][j]);
            }
            __syncthreads();
        }
    }
    float* Cp = C + bz * sC + (m0 + ty * 8) * ldc + n0 + tx * 8;
#pragma unroll
    for (int i = 0; i < 8; i++) {
#pragma unroll
        for (int j = 0; j < 8; j += 4) {
            float4 v;
            v.x = acc[i][j + 0]; v.y = acc[i][j + 1];
            v.z = acc[i][j + 2]; v.w = acc[i][j + 3];
            if (EPI == 1) {
                const long nb = n0 + tx * 8 + j;
                v.x = tanhf(v.x + bias[nb + 0]);
                v.y = tanhf(v.y + bias[nb + 1]);
                v.z = tanhf(v.z + bias[nb + 2]);
                v.w = tanhf(v.w + bias[nb + 3]);
            }
            *(float4*)(Cp + (long)i * ldc + j) = v;
        }
    }
#endif
}

// ---------------- softmax over S=1024 (==0 -> -inf fill) ----------------
// a-path: emits split-2 P planes (plane-interleaved tiles); fallback: fp32 in place.
__global__ void softmax_kernel(float* __restrict__ S, char* __restrict__ pP)
{
    const long row = blockIdx.x;
    float* p = S + (row << 10);
    const int tid = threadIdx.x;

    float4 xv = *(const float4*)(p + tid * 4);
    float v[4] = {xv.x, xv.y, xv.z, xv.w};
    float mx = -INFINITY;
#pragma unroll
    for (int i = 0; i < 4; i++) {
        if (v[i] == 0.0f) v[i] = -INFINITY;
        mx = fmaxf(mx, v[i]);
    }
    __shared__ float red[8];
#pragma unroll
    for (int o = 16; o; o >>= 1) mx = fmaxf(mx, __shfl_xor_sync(0xffffffffu, mx, o));
    if ((tid & 31) == 0) red[tid >> 5] = mx;
    __syncthreads();
    const float m = fmaxf(fmaxf(fmaxf(red[0], red[1]), fmaxf(red[2], red[3])),
                          fmaxf(fmaxf(red[4], red[5]), fmaxf(red[6], red[7])));
    __syncthreads();
    float s = 0.0f;
#pragma unroll
    for (int i = 0; i < 4; i++) { v[i] = expf(v[i] - m); s += v[i]; }
#pragma unroll
    for (int o = 16; o; o >>= 1) s += __shfl_xor_sync(0xffffffffu, s, o);
    if ((tid & 31) == 0) red[tid >> 5] = s;
    __syncthreads();
    const float inv = 1.0f / (red[0] + red[1] + red[2] + red[3] +
                              red[4] + red[5] + red[6] + red[7]);
#pragma unroll
    for (int i = 0; i < 4; i++) v[i] *= inv;

#if HAS_TCGEN05
    // split-2 trunc planes, tile (mBlk, chunk), plane-interleaved
    const long mBlk = row >> 7;
    const int r = (int)(row & 127);
    const int chunk = tid >> 4;
    const int cIn = (tid << 2) & 63;
    char* base = pP + (mBlk * 16 + chunk) * 32768L;
    uint32_t u[4], um[4];
#pragma unroll
    for (int q = 0; q < 4; ++q) {
        u[q] = __float_as_uint(v[q]);
        um[q] = __float_as_uint(v[q] - __uint_as_float(u[q] & 0xFFFF0000u));
    }
    const uint32_t bo = (r << 7) + (cIn << 1);
    const uint32_t sw = bo ^ ((bo >> 3) & 0x70);
    *(uint2*)(base + sw) = make_uint2(prmt_hi(u[0], u[1]), prmt_hi(u[2], u[3]));
    *(uint2*)(base + 16384 + sw) = make_uint2(prmt_hi(um[0], um[1]), prmt_hi(um[2], um[3]));
#else
    *(float4*)(p + tid * 4) = make_float4(v[0], v[1], v[2], v[3]);
#endif
}

// ---------------- enc [S,B,H] -> encT; a-path emits split-2 planes ----------------
__global__ void transpose_enc(const float* __restrict__ enc, float* __restrict__ encT,
                              char* __restrict__ etP)
{
    __shared__ float t[32][33];
    const int b  = blockIdx.z;
    const int s0 = blockIdx.x << 5;
    const int h0 = blockIdx.y << 5;
    const int tx = threadIdx.x, ty = threadIdx.y;  // 32x8
    const int tid = ty * 32 + tx;
#pragma unroll
    for (int j = 0; j < 4; ++j) {
        const int s = s0 + ty + j * 8;
        t[ty + j * 8][tx] = enc[(long)s * 32768 + b * 1024 + h0 + tx];
    }
    __syncthreads();
#if HAS_TCGEN05
    const int hIdx = tid >> 4;          // 0..15
    const int sp   = (tid & 15) << 1;   // 0,2,..,30
#pragma unroll
    for (int q = 0; q < 2; ++q) {
        const int hl = hIdx + (q << 4);
        const float v0 = t[sp][hl], v1 = t[sp + 1][hl];
        const int h = h0 + hl, s = s0 + sp;
        const int r = h & 127, hBlk = h >> 7;
        const int c = s & 63, sChunk = s >> 6;
        char* base = etP + (((long)b * 8 + hBlk) * 16 + sChunk) * 32768L;
        const uint32_t u0 = __float_as_uint(v0), u1 = __float_as_uint(v1);
        const uint32_t um0 = __float_as_uint(v0 - __uint_as_float(u0 & 0xFFFF0000u));
        const uint32_t um1 = __float_as_uint(v1 - __uint_as_float(u1 & 0xFFFF0000u));
        const uint32_t bo = (r << 7) + (c << 1);
        const uint32_t sw = bo ^ ((bo >> 3) & 0x70);
        *(uint32_t*)(base + sw) = prmt_hi(u0, u1);
        *(uint32_t*)(base + 16384 + sw) = prmt_hi(um0, um1);
    }
#else
#pragma unroll
    for (int j = 0; j < 4; ++j) {
        const int h = h0 + ty + j * 8;
        encT[((long)b << 20) + ((long)h << 10) + s0 + tx] = t[tx][ty + j * 8];
    }
#endif
}

// ---------------- launch ----------------
extern "C" void kernel_launch(void* const* d_in, const int* in_sizes, int n_in,
                              void* d_out, int out_size)
{
    const float* query = (const float*)d_in[0];  // [B,T,H]
    const float* enc   = (const float*)d_in[1];  // [S,B,H]
    const float* W_in  = (const float*)d_in[3];  // [H,H]
    const float* W_out = (const float*)d_in[4];  // [H,2H]
    const float* b_out = (const float*)d_in[5];  // [H]
    float* out = (float*)d_out;                  // [B,T,H]

    float *Z, *S, *Cc, *encT;
    cudaGetSymbolAddress((void**)&Z, g_Z);
    cudaGetSymbolAddress((void**)&S, g_S);
    cudaGetSymbolAddress((void**)&Cc, g_C);
    cudaGetSymbolAddress((void**)&encT, g_encT);
    char *wiP, *woP, *pP, *etP;
    cudaGetSymbolAddress((void**)&wiP, g_wiP);
    cudaGetSymbolAddress((void**)&woP, g_woP);
    cudaGetSymbolAddress((void**)&pP, g_pP);
    cudaGetSymbolAddress((void**)&etP, g_etP);

    const int SM3 = 1024 + 2 * 6 * 16384;  // 197,632 B
    const int SM2 = 1024 + 2 * 4 * 16384;  // 132,096 B
    cudaFuncSetAttribute(mma_gemm<3, 1, 0, 0, 1>, cudaFuncAttributeMaxDynamicSharedMemorySize, SM3);
    cudaFuncSetAttribute(mma_gemm<3, 1, 0, 0, 0>, cudaFuncAttributeMaxDynamicSharedMemorySize, SM3);
    cudaFuncSetAttribute(mma_gemm<2, 1, 0, 1, 1>, cudaFuncAttributeMaxDynamicSharedMemorySize, SM2);
    cudaFuncSetAttribute(mma_gemm<2, 2, 1, 0, 1>, cudaFuncAttributeMaxDynamicSharedMemorySize, SM2);

    // producers (cheap / free)
    split_w<3><<<dim3(16, 8), 256>>>(W_in, 1024, wiP);     // [nBlk 8][chunk 16]
    split_w<2><<<dim3(32, 8), 256>>>(W_out, 2048, woP);    // [nBlk 8][chunk 32]
    transpose_enc<<<dim3(32, 32, 32), dim3(32, 8)>>>(enc, encT, etP);

    // 1) Z = Q @ W_in^T   (split-3; B pre-split)
    mma_gemm<3, 1, 0, 0, 1><<<dim3(8, 128, 1), 256, SM3>>>(
        query, W_in, nullptr, nullptr, nullptr, wiP,
        16, 128, 8, 1024, 1024, 0, 0, 0, Z, 1024, nullptr);

    // 2) scores[b] = Z[b] @ enc[:,b,:]^T   (split-3; fully inline)
    mma_gemm<3, 1, 0, 0, 0><<<dim3(8, 4, 32), 256, SM3>>>(
        Z, enc, nullptr, nullptr, nullptr, nullptr,
        16, 4, 8, 1024, 32768, 512L * 1024, 1024, 512L * 1024, S, 1024, nullptr);

    // 3) softmax (with ==0 -> -inf quirk) -> split-2 P planes
    softmax_kernel<<<16384, 256>>>(S, pP);

    // 4) c[b] = P[b] @ encT[b]^T   (split-2; both operands pre-split -> pure copy loader)
    mma_gemm<2, 1, 0, 1, 1><<<dim3(8, 4, 32), 256, SM2>>>(
        S, encT, nullptr, nullptr, pP, etP,
        16, 4, 8, 1024, 1024, 512L * 1024, 1024L * 1024, 512L * 1024, Cc, 1024, nullptr);

    // 5) out = tanh(C @ Wout1^T + Q @ Wout2^T + b)   (split-2, NSEG=2; B pre-split)
    mma_gemm<2, 2, 1, 0, 1><<<dim3(8, 128, 1), 256, SM2>>>(
        Cc, W_out, query, W_out + 1024, nullptr, woP,
        16, 128, 8, 1024, 2048, 0, 0, 0, out, 1024, b_out);
}

// round 17
// speedup vs baseline: 1.9643x; 1.0418x over previous
#include <cuda_runtime.h>
#include <cuda_bf16.h>
#include <cstdint>
#include <math.h>

// tcgen05 is only available in the arch-specific ("a") compilation pass.
#if defined(__CUDA_ARCH_FEAT_SM103_ALL) || defined(__CUDA_ARCH_FEAT_SM100_ALL) || \
    defined(__CUDA_ARCH_FEAT_SM110_ALL) || defined(__CUDA_ARCH_FEAT_SM101_ALL)
#define HAS_TCGEN05 1
#else
#define HAS_TCGEN05 0
#endif

// ---------------- scratch (allocation-free rule) ----------------
__device__ float g_Z[32L * 512 * 1024];      // 64MB
__device__ float g_S[32L * 512 * 1024];      // 64MB  raw scores
__device__ float g_C[32L * 512 * 1024];      // 64MB  context (fp32)
__device__ float g_encT[32L * 1024 * 1024];  // 128MB fallback encT

// plane-interleaved split tiles: tile block = NSPLIT x 16KB contiguous
__device__ uint4 g_wiP[128L * 3 * 1024];        // W_in  split-3: 8x16 tiles, 6MB
__device__ uint4 g_woP[256L * 2 * 1024];        // W_out split-2: 8x32 tiles, 8MB
__device__ uint4 g_pP [2048L * 2 * 1024];       // P     split-2: 128x16 tiles, 64MB
__device__ uint4 g_etP[4096L * 2 * 1024];       // encT  split-2: 32x8x16 tiles, 128MB

// ---------------- helpers usable in all passes ----------------
__device__ __forceinline__ uint32_t prmt_hi(uint32_t a, uint32_t b) {
    uint32_t r;
    asm("prmt.b32 %0, %1, %2, 0x7632;" : "=r"(r) : "r"(a), "r"(b));
    return r;
}

// tile loader: fp32 -> NSPLIT bf16 planes via truncation split.
// tile = 128 rows x 64 cols; SW128 layout; planes spaced 16KB apart at s0.
// s0 may be SMEM or GMEM (generic stores). tid in [0,256).
template <int NSPLIT>
__device__ __forceinline__ void load_tile(char* s0, const float* __restrict__ g,
                                          long ld, int tid) {
    const int grp = tid >> 3;     // 0..31 (row group)
    const int c8  = tid & 7;      // 8 fp32 elements each
#pragma unroll
    for (int p = 0; p < 4; ++p) {
        const int r = grp + (p << 5);
        const float* src = g + (long)r * ld + (c8 << 3);
        const float4 v0 = *(const float4*)(src);
        const float4 v1 = *(const float4*)(src + 4);
        const float x[8] = {v0.x, v0.y, v0.z, v0.w, v1.x, v1.y, v1.z, v1.w};
        uint32_t w0[4], w1[4], w2[4];
#pragma unroll
        for (int j = 0; j < 4; ++j) {
            const float a = x[2 * j], b = x[2 * j + 1];
            const uint32_t ua = __float_as_uint(a), ub = __float_as_uint(b);
            w0[j] = prmt_hi(ua, ub);
            const float ma = a - __uint_as_float(ua & 0xFFFF0000u);
            const float mb = b - __uint_as_float(ub & 0xFFFF0000u);
            const uint32_t uma = __float_as_uint(ma), umb = __float_as_uint(mb);
            w1[j] = prmt_hi(uma, umb);
            if (NSPLIT == 3) {
                const float la = ma - __uint_as_float(uma & 0xFFFF0000u);
                const float lb = mb - __uint_as_float(umb & 0xFFFF0000u);
                w2[j] = prmt_hi(__float_as_uint(la), __float_as_uint(lb));
            }
        }
        const uint32_t bo = (r << 7) + (c8 << 4);
        const uint32_t sw = bo ^ ((bo >> 3) & 0x70);
        *(uint4*)(s0 + sw)         = make_uint4(w0[0], w0[1], w0[2], w0[3]);
        *(uint4*)(s0 + 16384 + sw) = make_uint4(w1[0], w1[1], w1[2], w1[3]);
        if (NSPLIT == 3)
            *(uint4*)(s0 + 32768 + sw) = make_uint4(w2[0], w2[1], w2[2], w2[3]);
    }
}

// contiguous NBYTES copy, 256 threads, 16B-aligned both sides
template <int NBYTES>
__device__ __forceinline__ void copyN(char* dst, const char* __restrict__ src, int tid) {
    const uint4* s = (const uint4*)src;
    uint4* d = (uint4*)dst;
#pragma unroll
    for (int i = 0; i < NBYTES / 4096; ++i) d[tid + i * 256] = s[tid + i * 256];
}

// pre-split a weight matrix into plane-interleaved swizzled tiles
template <int NSPLIT>
__global__ void split_w(const float* __restrict__ src, long ld, char* __restrict__ dst)
{
    const long tOff = ((long)blockIdx.y * gridDim.x + blockIdx.x) * (NSPLIT * 16384L);
    const float* g = src + ((long)blockIdx.y * 128) * ld + blockIdx.x * 64;
    load_tile<NSPLIT>(dst + tOff, g, ld, threadIdx.x);
}

#if HAS_TCGEN05
// ---------------- PTX helpers ----------------
__device__ __forceinline__ uint32_t smem_u32(const void* p) {
    uint32_t a;
    asm("{ .reg .u64 t; cvta.to.shared.u64 t, %1; cvt.u32.u64 %0, t; }" : "=r"(a) : "l"(p));
    return a;
}
__device__ __forceinline__ uint32_t elect_one() {
    uint32_t pred;
    asm volatile("{\n\t.reg .pred p;\n\telect.sync _|p, 0xFFFFFFFF;\n\tselp.b32 %0, 1, 0, p;\n\t}"
                 : "=r"(pred));
    return pred;
}

#define MBARRIER_INIT(addr, cnt) \
    asm volatile("mbarrier.init.shared.b64 [%0], %1;" :: "r"(addr), "r"(cnt) : "memory")

#define MBARRIER_WAIT_PARITY(mbar_smem_addr, phase_parity) do { \
    uint32_t _mbar = (uint32_t)(mbar_smem_addr); \
    uint32_t _parity = (uint32_t)(phase_parity); \
    uint32_t _done; \
    asm volatile( \
        "{\n\t.reg .pred p;\n\t" \
        "mbarrier.try_wait.parity.acquire.cta.shared::cta.b64 p, [%1], %2;\n\t" \
        "selp.b32 %0, 1, 0, p;\n\t}" \
        : "=r"(_done) : "r"(_mbar), "r"(_parity) : "memory"); \
    if (!_done) { \
        asm volatile( \
            "{\n\t.reg .pred P1;\n\t" \
            "WAIT_LOOP_%=:\n\t" \
            "mbarrier.try_wait.parity.acquire.cta.shared::cta.b64 P1, [%0], %1, 0x989680;\n\t" \
            "@P1 bra.uni WAIT_DONE_%=;\n\t" \
            "bra.uni WAIT_LOOP_%=;\n\t" \
            "WAIT_DONE_%=:\n\t}" \
            :: "r"(_mbar), "r"(_parity) : "memory"); \
    } \
} while (0)

#define TCGEN05_ALLOC(smem_addr, n) \
    asm volatile("tcgen05.alloc.cta_group::1.sync.aligned.shared::cta.b32 [%0], %1;" \
                 :: "r"((uint32_t)(smem_addr)), "r"((uint32_t)(n)) : "memory")
#define TCGEN05_DEALLOC(tm, n) \
    asm volatile("tcgen05.dealloc.cta_group::1.sync.aligned.b32 %0, %1;" :: "r"(tm), "r"((uint32_t)(n)))
#define TCGEN05_RELINQ() \
    asm volatile("tcgen05.relinquish_alloc_permit.cta_group::1.sync.aligned;")
#define TCGEN05_COMMIT(mb) \
    asm volatile("tcgen05.commit.cta_group::1.mbarrier::arrive::one.shared::cluster.b64 [%0];" \
                 :: "r"((uint32_t)(mb)) : "memory")
#define TCGEN05_FENCE_AFTER() asm volatile("tcgen05.fence::after_thread_sync;" ::: "memory")
#define TCGEN05_WAIT_LD()     asm volatile("tcgen05.wait::ld.sync.aligned;" ::: "memory")
#define FENCE_PROXY_ASYNC()   asm volatile("fence.proxy.async.shared::cta;" ::: "memory")

#define TCGEN05_LD_X32(r, tm) \
    asm volatile( \
        "tcgen05.ld.sync.aligned.32x32b.x32.b32 " \
        "{%0, %1, %2, %3, %4, %5, %6, %7, %8, %9, %10, %11, %12, %13, %14, %15, " \
        " %16, %17, %18, %19, %20, %21, %22, %23, %24, %25, %26, %27, %28, %29, %30, %31}, [%32];" \
        : "=r"((r)[0]),  "=r"((r)[1]),  "=r"((r)[2]),  "=r"((r)[3]), \
          "=r"((r)[4]),  "=r"((r)[5]),  "=r"((r)[6]),  "=r"((r)[7]), \
          "=r"((r)[8]),  "=r"((r)[9]),  "=r"((r)[10]), "=r"((r)[11]), \
          "=r"((r)[12]), "=r"((r)[13]), "=r"((r)[14]), "=r"((r)[15]), \
          "=r"((r)[16]), "=r"((r)[17]), "=r"((r)[18]), "=r"((r)[19]), \
          "=r"((r)[20]), "=r"((r)[21]), "=r"((r)[22]), "=r"((r)[23]), \
          "=r"((r)[24]), "=r"((r)[25]), "=r"((r)[26]), "=r"((r)[27]), \
          "=r"((r)[28]), "=r"((r)[29]), "=r"((r)[30]), "=r"((r)[31]) \
        : "r"(tm))

// SW128 SMEM descriptor (Blackwell): layout=2, version=1, SBO=64, LBO=1
static constexpr uint64_t DESC_BASE =
    (uint64_t(2) << 61) | (uint64_t(1) << 46) | (uint64_t(64) << 32) | (uint64_t(1) << 16);
__device__ __forceinline__ uint64_t make_desc(uint32_t addr) {
    return DESC_BASE | ((uint64_t)(addr >> 4) & 0x3FFF);
}

// cg1 SS bf16 MMA (f32 accum)
__device__ __forceinline__ void mma_ss(uint32_t d, uint64_t ad, uint64_t bd,
                                       uint32_t idesc, bool acc) {
    uint32_t e = acc ? 1u : 0u;
    asm volatile(
        "{\n\t.reg .pred p;\n\tsetp.ne.u32 p, %4, 0;\n\t"
        "tcgen05.mma.cta_group::1.kind::f16 [%0], %1, %2, %3, {%5, %5, %5, %5}, p;\n\t}"
        :: "r"(d), "l"(ad), "l"(bd), "r"(idesc), "r"(e), "r"(0u) : "memory");
}

// idesc: dtype=F32, a=BF16, b=BF16, N=128, M=128 (K-major both)
static constexpr uint32_t IDESC = (1u << 4) | (1u << 7) | (1u << 10) | (16u << 17) | (8u << 24);
#endif  // HAS_TCGEN05

// ---------------- main GEMM ----------------
// 288 threads: warps 0-7 (tid<256) = loaders, warp 8 = dedicated MMA issuer.
// C[bz][m,n] (+= over NSEG segs) = sum_k A[m,k] * B[n,k]
// APRE/BPRE: operand comes from pre-split plane-interleaved tiles (pure copy loader).
// EPI: 0 = fp32 store, 1 = tanh(x + bias[n]) store.
template <int NSPLIT, int NSEG, int EPI, int APRE, int BPRE>
__global__ void __launch_bounds__(288, 1)
mma_gemm(const float* A0, const float* B0, const float* A1, const float* B1,
         const char* aPl, const char* bPl,
         int K64, int mBPB, int nBPB,
         long lda, long ldb, long sA, long sB, long sC,
         float* __restrict__ C, int ldc, const float* __restrict__ bias)
{
    extern __shared__ char smem[];
    const int tid = threadIdx.x;
    const long m0 = (long)blockIdx.y * 128;
    const long n0 = (long)blockIdx.x * 128;
    const long bz = blockIdx.z;

#if HAS_TCGEN05
    constexpr int ARR   = 16384;
    constexpr int STAGE = NSPLIT * 2 * ARR;
    const uint32_t sb = smem_u32(smem);
    const int wid = tid >> 5, lid = tid & 31;
    const long aBlk = bz * mBPB + blockIdx.y;
    const long bBlk = bz * nBPB + blockIdx.x;
    const int K64T = NSEG * K64;

    if (wid == 8) TCGEN05_ALLOC(sb, 128);
    __syncthreads();
    uint32_t tmem;
    asm volatile("ld.shared.b32 %0, [%1];" : "=r"(tmem) : "r"(sb));
    if (tid == 0) { MBARRIER_INIT(sb + 8, 1); MBARRIER_INIT(sb + 16, 1); }
    __syncthreads();

    int ph0 = 0, ph1 = 0;

    auto load_chunk = [&](int c, char* st) {
        if (APRE) {
            copyN<NSPLIT * 16384>(st, aPl + (aBlk * K64T + c) * (NSPLIT * 16384L), tid);
        } else {
            const int seg = (NSEG == 2) ? (int)(c >= K64) : 0;
            const long kt = (long)(c - seg * K64) << 6;
            const float* Ag = (seg ? A1 : A0) + bz * sA + m0 * lda + kt;
            load_tile<NSPLIT>(st, Ag, lda, tid);
        }
        if (BPRE) {
            copyN<NSPLIT * 16384>(st + NSPLIT * ARR,
                                  bPl + (bBlk * K64T + c) * (NSPLIT * 16384L), tid);
        } else {
            const int seg = (NSEG == 2) ? (int)(c >= K64) : 0;
            const long kt = (long)(c - seg * K64) << 6;
            const float* Bg = (seg ? B1 : B0) + bz * sB + n0 * ldb + kt;
            load_tile<NSPLIT>(st + NSPLIT * ARR, Bg, ldb, tid);
        }
    };

    if (wid < 8) {
        load_chunk(0, smem + 1024);
        FENCE_PROXY_ASYNC();
    }
    __syncthreads();

#pragma unroll 1
    for (int c = 0; c < K64T; ++c) {
        const int s = c & 1;
        if (wid == 8) {
            if (elect_one()) {
                const uint32_t stb = sb + 1024 + s * STAGE;
                uint64_t dA[3], dB[3];
#pragma unroll
                for (int i = 0; i < NSPLIT; ++i) {
                    dA[i] = make_desc(stb + i * ARR);
                    dB[i] = make_desc(stb + (NSPLIT + i) * ARR);
                }
#pragma unroll
                for (int k = 0; k < 4; ++k) {
                    const uint64_t off = (uint64_t)(k * 2);
                    const bool first = (c == 0) && (k == 0);
                    if (NSPLIT == 3) {
                        mma_ss(tmem, dA[2] + off, dB[0] + off, IDESC, !first);
                        mma_ss(tmem, dA[0] + off, dB[2] + off, IDESC, true);
                        mma_ss(tmem, dA[1] + off, dB[1] + off, IDESC, true);
                        mma_ss(tmem, dA[1] + off, dB[0] + off, IDESC, true);
                        mma_ss(tmem, dA[0] + off, dB[1] + off, IDESC, true);
                        mma_ss(tmem, dA[0] + off, dB[0] + off, IDESC, true);
                    } else {
                        mma_ss(tmem, dA[1] + off, dB[0] + off, IDESC, !first);
                        mma_ss(tmem, dA[0] + off, dB[1] + off, IDESC, true);
                        mma_ss(tmem, dA[0] + off, dB[0] + off, IDESC, true);
                    }
                }
                TCGEN05_COMMIT(sb + 8 + s * 8);
            }
        }
        if (c + 1 < K64T) {
            const int s2 = (c + 1) & 1;
            if (c + 1 >= 2) {
                if (wid < 8) {
                    if (s2 == 0) { MBARRIER_WAIT_PARITY(sb + 8, ph0); }
                    else         { MBARRIER_WAIT_PARITY(sb + 16, ph1); }
                }
                if (s2 == 0) ph0 ^= 1; else ph1 ^= 1;
            }
            if (wid < 8) {
                load_chunk(c + 1, smem + 1024 + s2 * STAGE);
                FENCE_PROXY_ASYNC();
            }
            __syncthreads();
        }
    }

    {
        const int sl = (K64T - 1) & 1;
        if (sl == 0) { MBARRIER_WAIT_PARITY(sb + 8, ph0); }
        else         { MBARRIER_WAIT_PARITY(sb + 16, ph1); }
    }
    TCGEN05_FENCE_AFTER();

    if (wid < 4) {
        const long m = m0 + wid * 32 + lid;
        float* Crow = C + bz * sC + m * ldc + n0;
#pragma unroll 1
        for (int b4 = 0; b4 < 4; ++b4) {
            uint32_t r[32];
            TCGEN05_LD_X32(r, tmem + b4 * 32);
            TCGEN05_WAIT_LD();
#pragma unroll
            for (int j = 0; j < 32; j += 4) {
                float4 v;
                v.x = __uint_as_float(r[j + 0]);
                v.y = __uint_as_float(r[j + 1]);
                v.z = __uint_as_float(r[j + 2]);
                v.w = __uint_as_float(r[j + 3]);
                if (EPI == 1) {
                    const float* bb = bias + n0 + b4 * 32 + j;
                    v.x = tanhf(v.x + bb[0]);
                    v.y = tanhf(v.y + bb[1]);
                    v.z = tanhf(v.z + bb[2]);
                    v.w = tanhf(v.w + bb[3]);
                }
                *(float4*)(Crow + b4 * 32 + j) = v;
            }
        }
    }
    __syncthreads();
    if (wid == 8) {
        TCGEN05_RELINQ();
        TCGEN05_DEALLOC(tmem, 128);
    }

#else  // ---------------- fp32 FFMA fallback (non-"a" pass) ----------------
    if (tid >= 256) return;  // extra MMA-issue warp not used in fallback
    float (*As)[132] = (float(*)[132])smem;
    float (*Bs)[132] = (float(*)[132])(smem + 16 * 132 * 4);
    const int tx = tid & 15, ty = tid >> 4;
    const int K = K64 << 6;

    float acc[8][8];
#pragma unroll
    for (int i = 0; i < 8; i++)
#pragma unroll
        for (int j = 0; j < 8; j++) acc[i][j] = 0.0f;

    const int arow = tid >> 2, ac4 = (tid & 3) * 4;
#pragma unroll
    for (int seg = 0; seg < NSEG; ++seg) {
        const float* A = (seg == 0 ? A0 : A1) + bz * sA + m0 * lda;
        const float* B = (seg == 0 ? B0 : B1) + bz * sB + n0 * ldb;
        for (int kt = 0; kt < K; kt += 16) {
#pragma unroll
            for (int rr = 0; rr < 2; ++rr) {
                const int row = arow + rr * 64;
                float4 va = *(const float4*)(A + (long)row * lda + kt + ac4);
                As[ac4 + 0][row] = va.x; As[ac4 + 1][row] = va.y;
                As[ac4 + 2][row] = va.z; As[ac4 + 3][row] = va.w;
                float4 vb = *(const float4*)(B + (long)row * ldb + kt + ac4);
                Bs[ac4 + 0][row] = vb.x; Bs[ac4 + 1][row] = vb.y;
                Bs[ac4 + 2][row] = vb.z; Bs[ac4 + 3][row] = vb.w;
            }
            __syncthreads();
#pragma unroll
            for (int kk = 0; kk < 16; ++kk) {
                float a[8], b[8];
                *(float4*)&a[0] = *(const float4*)&As[kk][ty * 8];
                *(float4*)&a[4] = *(const float4*)&As[kk][ty * 8 + 4];
                *(float4*)&b[0] = *(const float4*)&Bs[kk][tx * 8];
                *(float4*)&b[4] = *(const float4*)&Bs[kk][tx * 8 + 4];
#pragma unroll
                for (int i = 0; i < 8; i++)
#pragma unroll
                    for (int j = 0; j < 8; j++)
                        acc[i][j] = fmaf(a[i], b[j], acc[i][j]);
            }
            __syncthreads();
        }
    }
    float* Cp = C + bz * sC + (m0 + ty * 8) * ldc + n0 + tx * 8;
#pragma unroll
    for (int i = 0; i < 8; i++) {
#pragma unroll
        for (int j = 0; j < 8; j += 4) {
            float4 v;
            v.x = acc[i][j + 0]; v.y = acc[i][j + 1];
            v.z = acc[i][j + 2]; v.w = acc[i][j + 3];
            if (EPI == 1) {
                const long nb = n0 + tx * 8 + j;
                v.x = tanhf(v.x + bias[nb + 0]);
                v.y = tanhf(v.y + bias[nb + 1]);
                v.z = tanhf(v.z + bias[nb + 2]);
                v.w = tanhf(v.w + bias[nb + 3]);
            }
            *(float4*)(Cp + (long)i * ldc + j) = v;
        }
    }
#endif
}

// ---------------- softmax over S=1024 (==0 -> -inf fill) ----------------
// a-path: emits split-2 P planes (plane-interleaved tiles); fallback: fp32 in place.
__global__ void softmax_kernel(float* __restrict__ S, char* __restrict__ pP)
{
    const long row = blockIdx.x;
    float* p = S + (row << 10);
    const int tid = threadIdx.x;

    float4 xv = *(const float4*)(p + tid * 4);
    float v[4] = {xv.x, xv.y, xv.z, xv.w};
    float mx = -INFINITY;
#pragma unroll
    for (int i = 0; i < 4; i++) {
        if (v[i] == 0.0f) v[i] = -INFINITY;
        mx = fmaxf(mx, v[i]);
    }
    __shared__ float red[8];
#pragma unroll
    for (int o = 16; o; o >>= 1) mx = fmaxf(mx, __shfl_xor_sync(0xffffffffu, mx, o));
    if ((tid & 31) == 0) red[tid >> 5] = mx;
    __syncthreads();
    const float m = fmaxf(fmaxf(fmaxf(red[0], red[1]), fmaxf(red[2], red[3])),
                          fmaxf(fmaxf(red[4], red[5]), fmaxf(red[6], red[7])));
    __syncthreads();
    float s = 0.0f;
#pragma unroll
    for (int i = 0; i < 4; i++) { v[i] = expf(v[i] - m); s += v[i]; }
#pragma unroll
    for (int o = 16; o; o >>= 1) s += __shfl_xor_sync(0xffffffffu, s, o);
    if ((tid & 31) == 0) red[tid >> 5] = s;
    __syncthreads();
    const float inv = 1.0f / (red[0] + red[1] + red[2] + red[3] +
                              red[4] + red[5] + red[6] + red[7]);
#pragma unroll
    for (int i = 0; i < 4; i++) v[i] *= inv;

#if HAS_TCGEN05
    // split-2 trunc planes, tile (mBlk, chunk), plane-interleaved
    const long mBlk = row >> 7;
    const int r = (int)(row & 127);
    const int chunk = tid >> 4;
    const int cIn = (tid << 2) & 63;
    char* base = pP + (mBlk * 16 + chunk) * 32768L;
    uint32_t u[4], um[4];
#pragma unroll
    for (int q = 0; q < 4; ++q) {
        u[q] = __float_as_uint(v[q]);
        um[q] = __float_as_uint(v[q] - __uint_as_float(u[q] & 0xFFFF0000u));
    }
    const uint32_t bo = (r << 7) + (cIn << 1);
    const uint32_t sw = bo ^ ((bo >> 3) & 0x70);
    *(uint2*)(base + sw) = make_uint2(prmt_hi(u[0], u[1]), prmt_hi(u[2], u[3]));
    *(uint2*)(base + 16384 + sw) = make_uint2(prmt_hi(um[0], um[1]), prmt_hi(um[2], um[3]));
#else
    *(float4*)(p + tid * 4) = make_float4(v[0], v[1], v[2], v[3]);
#endif
}

// ---------------- enc [S,B,H] -> encT; a-path emits split-2 planes ----------------
__global__ void transpose_enc(const float* __restrict__ enc, float* __restrict__ encT,
                              char* __restrict__ etP)
{
    __shared__ float t[32][33];
    const int b  = blockIdx.z;
    const int s0 = blockIdx.x << 5;
    const int h0 = blockIdx.y << 5;
    const int tx = threadIdx.x, ty = threadIdx.y;  // 32x8
    const int tid = ty * 32 + tx;
#pragma unroll
    for (int j = 0; j < 4; ++j) {
        const int s = s0 + ty + j * 8;
        t[ty + j * 8][tx] = enc[(long)s * 32768 + b * 1024 + h0 + tx];
    }
    __syncthreads();
#if HAS_TCGEN05
    const int hIdx = tid >> 4;          // 0..15
    const int sp   = (tid & 15) << 1;   // 0,2,..,30
#pragma unroll
    for (int q = 0; q < 2; ++q) {
        const int hl = hIdx + (q << 4);
        const float v0 = t[sp][hl], v1 = t[sp + 1][hl];
        const int h = h0 + hl, s = s0 + sp;
        const int r = h & 127, hBlk = h >> 7;
        const int c = s & 63, sChunk = s >> 6;
        char* base = etP + (((long)b * 8 + hBlk) * 16 + sChunk) * 32768L;
        const uint32_t u0 = __float_as_uint(v0), u1 = __float_as_uint(v1);
        const uint32_t um0 = __float_as_uint(v0 - __uint_as_float(u0 & 0xFFFF0000u));
        const uint32_t um1 = __float_as_uint(v1 - __uint_as_float(u1 & 0xFFFF0000u));
        const uint32_t bo = (r << 7) + (c << 1);
        const uint32_t sw = bo ^ ((bo >> 3) & 0x70);
        *(uint32_t*)(base + sw) = prmt_hi(u0, u1);
        *(uint32_t*)(base + 16384 + sw) = prmt_hi(um0, um1);
    }
#else
#pragma unroll
    for (int j = 0; j < 4; ++j) {
        const int h = h0 + ty + j * 8;
        encT[((long)b << 20) + ((long)h << 10) + s0 + tx] = t[tx][ty + j * 8];
    }
#endif
}

// ---------------- launch ----------------
extern "C" void kernel_launch(void* const* d_in, const int* in_sizes, int n_in,
                              void* d_out, int out_size)
{
    const float* query = (const float*)d_in[0];  // [B,T,H]
    const float* enc   = (const float*)d_in[1];  // [S,B,H]
    const float* W_in  = (const float*)d_in[3];  // [H,H]
    const float* W_out = (const float*)d_in[4];  // [H,2H]
    const float* b_out = (const float*)d_in[5];  // [H]
    float* out = (float*)d_out;                  // [B,T,H]

    float *Z, *S, *Cc, *encT;
    cudaGetSymbolAddress((void**)&Z, g_Z);
    cudaGetSymbolAddress((void**)&S, g_S);
    cudaGetSymbolAddress((void**)&Cc, g_C);
    cudaGetSymbolAddress((void**)&encT, g_encT);
    char *wiP, *woP, *pP, *etP;
    cudaGetSymbolAddress((void**)&wiP, g_wiP);
    cudaGetSymbolAddress((void**)&woP, g_woP);
    cudaGetSymbolAddress((void**)&pP, g_pP);
    cudaGetSymbolAddress((void**)&etP, g_etP);

    const int SM3 = 1024 + 2 * 6 * 16384;  // 197,632 B
    const int SM2 = 1024 + 2 * 4 * 16384;  // 132,096 B
    cudaFuncSetAttribute(mma_gemm<3, 1, 0, 0, 1>, cudaFuncAttributeMaxDynamicSharedMemorySize, SM3);
    cudaFuncSetAttribute(mma_gemm<3, 1, 0, 0, 0>, cudaFuncAttributeMaxDynamicSharedMemorySize, SM3);
    cudaFuncSetAttribute(mma_gemm<2, 1, 0, 1, 1>, cudaFuncAttributeMaxDynamicSharedMemorySize, SM2);
    cudaFuncSetAttribute(mma_gemm<2, 2, 1, 0, 1>, cudaFuncAttributeMaxDynamicSharedMemorySize, SM2);

    // producers (cheap / free)
    split_w<3><<<dim3(16, 8), 256>>>(W_in, 1024, wiP);     // [nBlk 8][chunk 16]
    split_w<2><<<dim3(32, 8), 256>>>(W_out, 2048, woP);    // [nBlk 8][chunk 32]
    transpose_enc<<<dim3(32, 32, 32), dim3(32, 8)>>>(enc, encT, etP);

    // 1) Z = Q @ W_in^T   (split-3; B pre-split)
    mma_gemm<3, 1, 0, 0, 1><<<dim3(8, 128, 1), 288, SM3>>>(
        query, W_in, nullptr, nullptr, nullptr, wiP,
        16, 128, 8, 1024, 1024, 0, 0, 0, Z, 1024, nullptr);

    // 2) scores[b] = Z[b] @ enc[:,b,:]^T   (split-3; fully inline)
    mma_gemm<3, 1, 0, 0, 0><<<dim3(8, 4, 32), 288, SM3>>>(
        Z, enc, nullptr, nullptr, nullptr, nullptr,
        16, 4, 8, 1024, 32768, 512L * 1024, 1024, 512L * 1024, S, 1024, nullptr);

    // 3) softmax (with ==0 -> -inf quirk) -> split-2 P planes
    softmax_kernel<<<16384, 256>>>(S, pP);

    // 4) c[b] = P[b] @ encT[b]^T   (split-2; both operands pre-split -> pure copy loader)
    mma_gemm<2, 1, 0, 1, 1><<<dim3(8, 4, 32), 288, SM2>>>(
        S, encT, nullptr, nullptr, pP, etP,
        16, 4, 8, 1024, 1024, 512L * 1024, 1024L * 1024, 512L * 1024, Cc, 1024, nullptr);

    // 5) out = tanh(C @ Wout1^T + Q @ Wout2^T + b)   (split-2, NSEG=2; B pre-split)
    mma_gemm<2, 2, 1, 0, 1><<<dim3(8, 128, 1), 288, SM2>>>(
        Cc, W_out, query, W_out + 1024, nullptr, woP,
        16, 128, 8, 1024, 2048, 0, 0, 0, out, 1024, b_out);
}